// round 2
// baseline (speedup 1.0000x reference)
#include <cuda_runtime.h>
#include <math.h>
#include <stdint.h>

#define TM 128
#define NT 256

// -------- scratch (no allocations allowed) --------
#define MAX_ATOMS 100000
__device__ float g_b2a[MAX_ATOMS * 32];
__device__ float g_cnt[MAX_ATOMS];
__device__ float g_bsum[32];
__device__ float g_asum[32];

__device__ __forceinline__ float selu_f(float x) {
    const float lam = 1.0507009873554805f;
    const float la  = 1.7580993408473766f;  // lam * alpha
    return x > 0.f ? lam * x : la * expm1f(x);
}

// ---- Blackwell packed fp32 helpers (ptxas never emits these from C++) ----
#define FMA_F32X2(acc, a, b) \
    asm("fma.rn.f32x2 %0, %1, %2, %0;" : "+l"(acc) : "l"(a), "l"(b))

#define PACK_DUP_F32X2(out, v) \
    asm("mov.b64 %0, {%1, %1};" : "=l"(out) : "r"(__float_as_uint(v)))

#define UNPACK_F32X2(lo, hi, in) \
    do { unsigned _ulo, _uhi; \
         asm("mov.b64 {%0, %1}, %2;" : "=r"(_ulo), "=r"(_uhi) : "l"(in)); \
         lo = __uint_as_float(_ulo); hi = __uint_as_float(_uhi); } while (0)

// H[j][m] (ld 132, j<64) = selu( X[k][m] (ld 132, K rows) @ W[K][64] + B )
// 256 threads: 16 m-tiles (8 rows = 4 row-pairs) x 16 j-tiles (4 cols)
__device__ __forceinline__ void dense64(const float* X, const float* W,
                                        const float* B, float* H, int K)
{
    const int tid = threadIdx.x;
    const int tm = (tid & 15) << 3;
    const int tj = (tid >> 4) << 2;

    unsigned long long acc2[4][4];  // [row-pair][col]
#pragma unroll
    for (int p = 0; p < 4; p++)
#pragma unroll
        for (int c = 0; c < 4; c++) acc2[p][c] = 0ull;

    const ulonglong2* xp = (const ulonglong2*)(X + tm);
    const float* wp = W + tj;
#pragma unroll 2
    for (int k = 0; k < K; k++) {
        float4 w = *(const float4*)wp;
        ulonglong2 xa = xp[0];
        ulonglong2 xb = xp[1];
        unsigned long long xpair[4] = {xa.x, xa.y, xb.x, xb.y};
        unsigned long long wd[4];
        PACK_DUP_F32X2(wd[0], w.x);
        PACK_DUP_F32X2(wd[1], w.y);
        PACK_DUP_F32X2(wd[2], w.z);
        PACK_DUP_F32X2(wd[3], w.w);
#pragma unroll
        for (int p = 0; p < 4; p++)
#pragma unroll
            for (int c = 0; c < 4; c++)
                FMA_F32X2(acc2[p][c], xpair[p], wd[c]);
        xp += 33;   // 132 floats = 33 ulonglong2
        wp += 64;
    }
    __syncthreads();  // everyone done reading X (H may alias X rows)
#pragma unroll
    for (int c = 0; c < 4; c++) {
        float b = B[tj + c];
        float* hrow = H + (tj + c) * 132 + tm;
#pragma unroll
        for (int p = 0; p < 4; p++) {
            float lo, hi;
            UNPACK_F32X2(lo, hi, acc2[p][c]);
            hrow[2 * p]     = selu_f(lo + b);
            hrow[2 * p + 1] = selu_f(hi + b);
        }
    }
    __syncthreads();
}

// H3[m][j] (ld 36, j<32) = selu( X[k][m] @ W[K][32] + B )
__device__ __forceinline__ void dense32(const float* X, const float* W,
                                        const float* B, float* H3, int K)
{
    const int tid = threadIdx.x;
    const int tm = (tid & 15) << 3;
    const int tj = (tid >> 4) << 1;  // 0..30

    unsigned long long acc2[4][2];
#pragma unroll
    for (int p = 0; p < 4; p++) { acc2[p][0] = 0ull; acc2[p][1] = 0ull; }

    const ulonglong2* xp = (const ulonglong2*)(X + tm);
    const float* wp = W + tj;
#pragma unroll 2
    for (int k = 0; k < K; k++) {
        float2 w = *(const float2*)wp;
        ulonglong2 xa = xp[0];
        ulonglong2 xb = xp[1];
        unsigned long long xpair[4] = {xa.x, xa.y, xb.x, xb.y};
        unsigned long long wd[2];
        PACK_DUP_F32X2(wd[0], w.x);
        PACK_DUP_F32X2(wd[1], w.y);
#pragma unroll
        for (int p = 0; p < 4; p++) {
            FMA_F32X2(acc2[p][0], xpair[p], wd[0]);
            FMA_F32X2(acc2[p][1], xpair[p], wd[1]);
        }
        xp += 33;
        wp += 32;
    }
    __syncthreads();
    float b0 = B[tj], b1 = B[tj + 1];
#pragma unroll
    for (int p = 0; p < 4; p++) {
        float lo0, hi0, lo1, hi1;
        UNPACK_F32X2(lo0, hi0, acc2[p][0]);
        UNPACK_F32X2(lo1, hi1, acc2[p][1]);
        int m = tm + 2 * p;
        H3[m * 36 + tj]           = selu_f(lo0 + b0);
        H3[(m + 1) * 36 + tj]     = selu_f(hi0 + b0);
        H3[m * 36 + tj + 1]       = selu_f(lo1 + b1);
        H3[(m + 1) * 36 + tj + 1] = selu_f(hi1 + b1);
    }
    __syncthreads();
}

// ------------------------- zero scratch -------------------------
__global__ void zero_kernel(int n_atoms)
{
    int i = blockIdx.x * blockDim.x + threadIdx.x;
    int stride = gridDim.x * blockDim.x;
    int nb = n_atoms * 32;
    for (int idx = i; idx < nb; idx += stride) g_b2a[idx] = 0.f;
    for (int idx = i; idx < n_atoms; idx += stride) g_cnt[idx] = 0.f;
    if (i < 32) { g_bsum[i] = 0.f; g_asum[i] = 0.f; }
}

// ------------------------- phi_e over bonds -------------------------
__global__ void __launch_bounds__(NT, 1) bond_kernel(
    const float* __restrict__ bonds, const int* __restrict__ ba1,
    const int* __restrict__ ba2, const float* __restrict__ atoms,
    const float* __restrict__ state,
    const float* __restrict__ ew1, const float* __restrict__ eb1,
    const float* __restrict__ ew2, const float* __restrict__ eb2,
    const float* __restrict__ ew3, const float* __restrict__ eb3,
    float* __restrict__ out_bonds, int n_bonds)
{
    extern __shared__ float s[];
    float* Ws1 = s;                   // 8192
    float* Ws2 = Ws1 + 8192;          // 4096
    float* Ws3 = Ws2 + 4096;          // 2048
    float* Bs1 = Ws3 + 2048;          // 64
    float* Bs2 = Bs1 + 64;            // 64
    float* Bs3 = Bs2 + 64;            // 32
    float* Xs  = Bs3 + 32;            // 128*132 (H1 rows 0..63, H2 rows 64..127 reuse)
    float* H3  = Xs + 128 * 132;      // 128*36
    int*   A1s = (int*)(H3 + 128 * 36);  // 128
    int*   A2s = A1s + 128;              // 128

    const int tid = threadIdx.x;
    const int base = blockIdx.x * TM;

    for (int i = tid; i < 8192; i += NT) Ws1[i] = ew1[i];
    for (int i = tid; i < 4096; i += NT) Ws2[i] = ew2[i];
    for (int i = tid; i < 2048; i += NT) Ws3[i] = ew3[i];
    if (tid < 64) { Bs1[tid] = eb1[tid]; Bs2[tid] = eb2[tid]; }
    if (tid < 32) Bs3[tid] = eb3[tid];
    if (tid < TM) {
        A1s[tid] = ba1[base + tid];
        A2s[tid] = ba2[base + tid];
    }
    __syncthreads();

    // gather + concat into Xs[k][m]; k: 0..31 a1 | 32..63 a2 | 64..95 bond | 96..127 state
    for (int idx = tid; idx < TM * 32; idx += NT) {
        int m = idx >> 5, q = idx & 31;
        int seg = q >> 3, f4 = q & 7;
        const float* src;
        if (seg == 0)      src = atoms + (size_t)A1s[m] * 32;
        else if (seg == 1) src = atoms + (size_t)A2s[m] * 32;
        else if (seg == 2) src = bonds + (size_t)(base + m) * 32;
        else               src = state;
        float4 v = *(const float4*)(src + (f4 << 2));
        int k = (seg << 5) + (f4 << 2);
        Xs[(k + 0) * 132 + m] = v.x;
        Xs[(k + 1) * 132 + m] = v.y;
        Xs[(k + 2) * 132 + m] = v.z;
        Xs[(k + 3) * 132 + m] = v.w;
    }
    __syncthreads();

    dense64(Xs, Ws1, Bs1, Xs, 128);             // H1 -> Xs rows 0..63
    dense64(Xs, Ws2, Bs2, Xs + 64 * 132, 64);   // H2 -> Xs rows 64..127
    dense32(Xs + 64 * 132, Ws3, Bs3, H3, 64);   // H3[m][j]

    // bonds_new out (coalesced float4)
    for (int idx = tid; idx < TM * 8; idx += NT) {
        int m = idx >> 3, f4 = idx & 7;
        float4 v = *(float4*)&H3[m * 36 + (f4 << 2)];
        *(float4*)&out_bonds[(size_t)(base + m) * 32 + (f4 << 2)] = v;
    }
    // scatter-add to atom1 rows (one 128B row per bond, coalesced RED)
    {
        int lane = tid & 31, w = tid >> 5;
        for (int m = w; m < TM; m += 8)
            atomicAdd(&g_b2a[(size_t)A1s[m] * 32 + lane], H3[m * 36 + lane]);
    }
    if (tid < TM) atomicAdd(&g_cnt[A1s[tid]], 1.0f);
    // partial column sums for mean(bonds_new)
    if (tid < 32) {
        float ssum = 0.f;
        for (int m = 0; m < TM; m++) ssum += H3[m * 36 + tid];
        atomicAdd(&g_bsum[tid], ssum);
    }
}

// ------------------------- phi_v over atoms -------------------------
__global__ void __launch_bounds__(NT, 1) atom_kernel(
    const float* __restrict__ atoms, const float* __restrict__ state,
    const float* __restrict__ vw1, const float* __restrict__ vb1,
    const float* __restrict__ vw2, const float* __restrict__ vb2,
    const float* __restrict__ vw3, const float* __restrict__ vb3,
    float* __restrict__ out_atoms, int n_atoms)
{
    extern __shared__ float s[];
    float* Ws1 = s;                    // 6144 (96x64)
    float* Ws2 = Ws1 + 6144;           // 4096
    float* Ws3 = Ws2 + 4096;           // 2048
    float* Bs1 = Ws3 + 2048;           // 64
    float* Bs2 = Bs1 + 64;             // 64
    float* Bs3 = Bs2 + 64;             // 32
    float* Xs  = Bs3 + 32;             // 96*132 (H1 reuses rows 0..63)
    float* H2  = Xs + 96 * 132;        // 64*132
    float* H3  = H2 + 64 * 132;        // 128*36

    const int tid = threadIdx.x;
    const int base = blockIdx.x * TM;

    for (int i = tid; i < 6144; i += NT) Ws1[i] = vw1[i];
    for (int i = tid; i < 4096; i += NT) Ws2[i] = vw2[i];
    for (int i = tid; i < 2048; i += NT) Ws3[i] = vw3[i];
    if (tid < 64) { Bs1[tid] = vb1[tid]; Bs2[tid] = vb2[tid]; }
    if (tid < 32) Bs3[tid] = vb3[tid];
    __syncthreads();

    // rows 0..31: b2a / cnt
    for (int idx = tid; idx < TM * 8; idx += NT) {
        int m = idx >> 3, f4 = idx & 7;
        int gm = base + m;
        int id = gm < n_atoms ? gm : n_atoms - 1;
        float c = g_cnt[id];
        float4 v = *(const float4*)&g_b2a[(size_t)id * 32 + (f4 << 2)];
        int k = f4 << 2;
        Xs[(k + 0) * 132 + m] = v.x / c;
        Xs[(k + 1) * 132 + m] = v.y / c;
        Xs[(k + 2) * 132 + m] = v.z / c;
        Xs[(k + 3) * 132 + m] = v.w / c;
    }
    // rows 32..63: atoms
    for (int idx = tid; idx < TM * 8; idx += NT) {
        int m = idx >> 3, f4 = idx & 7;
        int gm = base + m;
        int id = gm < n_atoms ? gm : n_atoms - 1;
        float4 v = *(const float4*)&atoms[(size_t)id * 32 + (f4 << 2)];
        int k = 32 + (f4 << 2);
        Xs[(k + 0) * 132 + m] = v.x;
        Xs[(k + 1) * 132 + m] = v.y;
        Xs[(k + 2) * 132 + m] = v.z;
        Xs[(k + 3) * 132 + m] = v.w;
    }
    // rows 64..95: state (broadcast)
    for (int idx = tid; idx < TM * 8; idx += NT) {
        int m = idx >> 3, f4 = idx & 7;
        float4 v = *(const float4*)&state[f4 << 2];
        int k = 64 + (f4 << 2);
        Xs[(k + 0) * 132 + m] = v.x;
        Xs[(k + 1) * 132 + m] = v.y;
        Xs[(k + 2) * 132 + m] = v.z;
        Xs[(k + 3) * 132 + m] = v.w;
    }
    __syncthreads();

    dense64(Xs, Ws1, Bs1, Xs, 96);
    dense64(Xs, Ws2, Bs2, H2, 64);
    dense32(H2, Ws3, Bs3, H3, 64);

    for (int idx = tid; idx < TM * 8; idx += NT) {
        int m = idx >> 3, f4 = idx & 7;
        int gm = base + m;
        if (gm < n_atoms) {
            float4 v = *(float4*)&H3[m * 36 + (f4 << 2)];
            *(float4*)&out_atoms[(size_t)gm * 32 + (f4 << 2)] = v;
        }
    }
    if (tid < 32) {
        float ssum = 0.f;
        for (int m = 0; m < TM; m++)
            if (base + m < n_atoms) ssum += H3[m * 36 + tid];
        atomicAdd(&g_asum[tid], ssum);
    }
}

// ------------------------- phi_u (single tile) -------------------------
__global__ void state_kernel(
    const float* __restrict__ state,
    const float* __restrict__ uw1, const float* __restrict__ ub1,
    const float* __restrict__ uw2, const float* __restrict__ ub2,
    const float* __restrict__ uw3, const float* __restrict__ ub3,
    float* __restrict__ out_state, int n_bonds, int n_atoms)
{
    __shared__ float x[96], h1[64], h2[64];
    int tid = threadIdx.x;  // 64 threads
    if (tid < 32) {
        x[tid]      = g_bsum[tid] / (float)n_bonds;
        x[32 + tid] = g_asum[tid] / (float)n_atoms;
        x[64 + tid] = state[tid];
    }
    __syncthreads();
    {
        float a = ub1[tid];
        for (int k = 0; k < 96; k++) a = fmaf(x[k], uw1[k * 64 + tid], a);
        h1[tid] = selu_f(a);
    }
    __syncthreads();
    {
        float a = ub2[tid];
        for (int k = 0; k < 64; k++) a = fmaf(h1[k], uw2[k * 64 + tid], a);
        h2[tid] = selu_f(a);
    }
    __syncthreads();
    if (tid < 32) {
        float a = ub3[tid];
        for (int k = 0; k < 64; k++) a = fmaf(h2[k], uw3[k * 32 + tid], a);
        out_state[tid] = selu_f(a);
    }
}

// ------------------------- launch -------------------------
extern "C" void kernel_launch(void* const* d_in, const int* in_sizes, int n_in,
                              void* d_out, int out_size)
{
    const float* bonds = (const float*)d_in[0];
    const int*   ba1   = (const int*)d_in[1];
    const int*   ba2   = (const int*)d_in[2];
    const float* atoms = (const float*)d_in[3];
    const float* state = (const float*)d_in[4];
    const float* ew1 = (const float*)d_in[5];
    const float* eb1 = (const float*)d_in[6];
    const float* ew2 = (const float*)d_in[7];
    const float* eb2 = (const float*)d_in[8];
    const float* ew3 = (const float*)d_in[9];
    const float* eb3 = (const float*)d_in[10];
    const float* vw1 = (const float*)d_in[11];
    const float* vb1 = (const float*)d_in[12];
    const float* vw2 = (const float*)d_in[13];
    const float* vb2 = (const float*)d_in[14];
    const float* vw3 = (const float*)d_in[15];
    const float* vb3 = (const float*)d_in[16];
    const float* uw1 = (const float*)d_in[17];
    const float* ub1 = (const float*)d_in[18];
    const float* uw2 = (const float*)d_in[19];
    const float* ub2 = (const float*)d_in[20];
    const float* uw3 = (const float*)d_in[21];
    const float* ub3 = (const float*)d_in[22];

    const int n_bonds = in_sizes[1];
    const int n_atoms = in_sizes[3] / 32;

    float* out        = (float*)d_out;
    float* out_bonds  = out;
    float* out_atoms  = out + (size_t)n_bonds * 32;
    float* out_state  = out_atoms + (size_t)n_atoms * 32;

    const int BOND_SMEM = (8192 + 4096 + 2048 + 160 + 128 * 132 + 128 * 36) * 4 + 256 * 4;
    const int ATOM_SMEM = (6144 + 4096 + 2048 + 160 + 96 * 132 + 64 * 132 + 128 * 36) * 4;

    cudaFuncSetAttribute(bond_kernel, cudaFuncAttributeMaxDynamicSharedMemorySize, BOND_SMEM);
    cudaFuncSetAttribute(atom_kernel, cudaFuncAttributeMaxDynamicSharedMemorySize, ATOM_SMEM);

    zero_kernel<<<256, 256>>>(n_atoms);

    int bond_blocks = (n_bonds + TM - 1) / TM;
    bond_kernel<<<bond_blocks, NT, BOND_SMEM>>>(
        bonds, ba1, ba2, atoms, state,
        ew1, eb1, ew2, eb2, ew3, eb3, out_bonds, n_bonds);

    int atom_blocks = (n_atoms + TM - 1) / TM;
    atom_kernel<<<atom_blocks, NT, ATOM_SMEM>>>(
        atoms, state, vw1, vb1, vw2, vb2, vw3, vb3, out_atoms, n_atoms);

    state_kernel<<<1, 64>>>(state, uw1, ub1, uw2, ub2, uw3, ub3,
                            out_state, n_bonds, n_atoms);
}

// round 4
// speedup vs baseline: 2.3126x; 2.3126x over previous
#include <cuda_runtime.h>
#include <cuda_bf16.h>
#include <math.h>
#include <stdint.h>

// ================= scratch (no allocations allowed) =================
#define MAX_ATOMS 100000
__device__ float g_b2a[MAX_ATOMS * 32];
__device__ float g_cnt[MAX_ATOMS];
__device__ float g_bsum[32];
__device__ float g_asum[32];

// pre-transposed bf16 weight images Wt[n][k], hi/lo split, padded k-stride
// e-side: W1 [64][136] x2, W2 [64][72] x2, W3 [32][72] x2  = 31232 elems
// v-side: V1 [64][104] x2, V2 [64][72] x2, V3 [32][72] x2  = 27136 elems
__device__ __align__(16) __nv_bfloat16 g_we[31232];
__device__ __align__(16) __nv_bfloat16 g_wv[27136];

// element offsets inside g_we / g_wv
#define EW1H 0
#define EW1L 8704
#define EW2H 17408
#define EW2L 22016
#define EW3H 26624
#define EW3L 28928
#define VW1H 0
#define VW1L 6656
#define VW2H 13312
#define VW2L 17920
#define VW3H 22528
#define VW3L 24832

__device__ __forceinline__ float selu_f(float x) {
    const float lam = 1.0507009873554805f;
    const float la  = 1.7580993408473766f;  // lam * alpha
    return x > 0.f ? lam * x : la * expm1f(x);
}

// fp32 pair -> bf16x2 hi word + bf16x2 residual word
__device__ __forceinline__ void split_pair(float v0, float v1, uint32_t& hw, uint32_t& lw) {
    __nv_bfloat16 h0 = __float2bfloat16(v0), h1 = __float2bfloat16(v1);
    __nv_bfloat162 hp; hp.x = h0; hp.y = h1;
    __nv_bfloat162 lp;
    lp.x = __float2bfloat16(v0 - __bfloat162float(h0));
    lp.y = __float2bfloat16(v1 - __bfloat162float(h1));
    hw = *(uint32_t*)&hp;
    lw = *(uint32_t*)&lp;
}

// ---- m16n8k16 bf16 MMA (baseline ISA, valid on .target sm_100) ----
__device__ __forceinline__ void mma_bf16(float c[4], const uint32_t a[4], const uint32_t b[2]) {
    asm volatile(
        "mma.sync.aligned.m16n8k16.row.col.f32.bf16.bf16.f32 "
        "{%0,%1,%2,%3}, {%4,%5,%6,%7}, {%8,%9}, {%0,%1,%2,%3};"
        : "+f"(c[0]), "+f"(c[1]), "+f"(c[2]), "+f"(c[3])
        : "r"(a[0]), "r"(a[1]), "r"(a[2]), "r"(a[3]), "r"(b[0]), "r"(b[1]));
}

// A fragment (16x16, row-major image, saw = words per row); kw = k*8 + t
__device__ __forceinline__ void ldA(uint32_t a[4], const uint32_t* img, int row, int saw, int kw) {
    a[0] = img[row * saw + kw];
    a[1] = img[(row + 8) * saw + kw];
    a[2] = img[row * saw + kw + 4];
    a[3] = img[(row + 8) * saw + kw + 4];
}
// B fragment (16x8 col-major == Wt[n][k] row-major image)
__device__ __forceinline__ void ldB(uint32_t b[2], const uint32_t* img, int nrow, int sbw, int kw) {
    b[0] = img[nrow * sbw + kw];
    b[1] = img[nrow * sbw + kw + 4];
}

// one dense layer: acc[2][NTW][4] += A(128xK) @ Wt^T  (3-pass bf16 split)
template <int KS, int NTW>
__device__ __forceinline__ void mlp_layer(
    const uint32_t* Ah, const uint32_t* Al, int saw,
    const uint32_t* Bh, const uint32_t* Bl, int sbw,
    int wm, int wn, int g, int t, float acc[2][NTW][4])
{
#pragma unroll
    for (int i = 0; i < 2; i++)
#pragma unroll
        for (int j = 0; j < NTW; j++)
#pragma unroll
            for (int q = 0; q < 4; q++) acc[i][j][q] = 0.f;

#pragma unroll
    for (int k = 0; k < KS; k++) {
        const int kw = k * 8 + t;
        uint32_t ah[2][4], al[2][4];
#pragma unroll
        for (int i = 0; i < 2; i++) {
            int row = wm * 32 + i * 16 + g;
            ldA(ah[i], Ah, row, saw, kw);
            ldA(al[i], Al, row, saw, kw);
        }
#pragma unroll
        for (int j = 0; j < NTW; j++) {
            int nrow = (wn * NTW + j) * 8 + g;
            uint32_t bh[2], bl[2];
            ldB(bh, Bh, nrow, sbw, kw);
            ldB(bl, Bl, nrow, sbw, kw);
#pragma unroll
            for (int i = 0; i < 2; i++) {
                mma_bf16(acc[i][j], ah[i], bh);
                mma_bf16(acc[i][j], ah[i], bl);
                mma_bf16(acc[i][j], al[i], bh);
            }
        }
    }
}

// epilogue: bias+selu -> split -> bf16 H images (stride shw words)
template <int NTW>
__device__ __forceinline__ void epi_to_h(
    float acc[2][NTW][4], const float* bias,
    uint32_t* Hh, uint32_t* Hl, int shw,
    int wm, int wn, int g, int t)
{
#pragma unroll
    for (int i = 0; i < 2; i++) {
        int row = wm * 32 + i * 16 + g;
#pragma unroll
        for (int j = 0; j < NTW; j++) {
            int col = (wn * NTW + j) * 8 + 2 * t;
            int cw  = (wn * NTW + j) * 4 + t;
            float b0 = bias[col], b1 = bias[col + 1];
            uint32_t hw, lw;
            split_pair(selu_f(acc[i][j][0] + b0), selu_f(acc[i][j][1] + b1), hw, lw);
            Hh[row * shw + cw] = hw;
            Hl[row * shw + cw] = lw;
            split_pair(selu_f(acc[i][j][2] + b0), selu_f(acc[i][j][3] + b1), hw, lw);
            Hh[(row + 8) * shw + cw] = hw;
            Hl[(row + 8) * shw + cw] = lw;
        }
    }
}

// epilogue: bias+selu -> fp32 H3 staging [128][36]
template <int NTW>
__device__ __forceinline__ void epi_to_f32(
    float acc[2][NTW][4], const float* bias, float* H3,
    int wm, int wn, int g, int t)
{
#pragma unroll
    for (int i = 0; i < 2; i++) {
        int row = wm * 32 + i * 16 + g;
#pragma unroll
        for (int j = 0; j < NTW; j++) {
            int col = (wn * NTW + j) * 8 + 2 * t;
            float b0 = bias[col], b1 = bias[col + 1];
            float2 v;
            v.x = selu_f(acc[i][j][0] + b0);
            v.y = selu_f(acc[i][j][1] + b1);
            *(float2*)&H3[row * 36 + col] = v;
            v.x = selu_f(acc[i][j][2] + b0);
            v.y = selu_f(acc[i][j][3] + b1);
            *(float2*)&H3[(row + 8) * 36 + col] = v;
        }
    }
}

// ================= zero scratch =================
__global__ void zero_kernel(int n_atoms)
{
    int i = blockIdx.x * blockDim.x + threadIdx.x;
    int stride = gridDim.x * blockDim.x;
    int nb = n_atoms * 32;
    for (int idx = i; idx < nb; idx += stride) g_b2a[idx] = 0.f;
    for (int idx = i; idx < n_atoms; idx += stride) g_cnt[idx] = 0.f;
    if (i < 32) { g_bsum[i] = 0.f; g_asum[i] = 0.f; }
}

// ================= weight transpose + split prep =================
// src W[k][n] row-major; dst image Wt[n][k] (k-stride padded), hi & lo
__global__ void prep_kernel(
    const float* __restrict__ ew1, const float* __restrict__ ew2, const float* __restrict__ ew3,
    const float* __restrict__ vw1, const float* __restrict__ vw2, const float* __restrict__ vw3)
{
    int i = blockIdx.x * blockDim.x + threadIdx.x;
    if (i >= 29184) return;
    const float* src; __nv_bfloat16 *ih, *il;
    int stride, N, Ksrc, local;
    if (i < 8704)        { local = i;         stride = 136; N = 64; Ksrc = 128; src = ew1; ih = g_we + EW1H; il = g_we + EW1L; }
    else if (i < 13312)  { local = i - 8704;  stride = 72;  N = 64; Ksrc = 64;  src = ew2; ih = g_we + EW2H; il = g_we + EW2L; }
    else if (i < 15616)  { local = i - 13312; stride = 72;  N = 32; Ksrc = 64;  src = ew3; ih = g_we + EW3H; il = g_we + EW3L; }
    else if (i < 22272)  { local = i - 15616; stride = 104; N = 64; Ksrc = 96;  src = vw1; ih = g_wv + VW1H; il = g_wv + VW1L; }
    else if (i < 26880)  { local = i - 22272; stride = 72;  N = 64; Ksrc = 64;  src = vw2; ih = g_wv + VW2H; il = g_wv + VW2L; }
    else                 { local = i - 26880; stride = 72;  N = 32; Ksrc = 64;  src = vw3; ih = g_wv + VW3H; il = g_wv + VW3L; }
    int n = local / stride, k = local % stride;
    float w = (k < Ksrc) ? src[k * N + n] : 0.f;
    __nv_bfloat16 h = __float2bfloat16(w);
    __nv_bfloat16 l = __float2bfloat16(w - __bfloat162float(h));
    ih[local] = h;
    il[local] = l;
}

// ================= smem maps (bytes) =================
// bond:
#define B_BIAS   0        // 160 floats
#define B_A1S    640      // 128 ints
#define B_XB     1280     // activation region, 69632 B
#define B_WB     70912    // weight images, 62464 B
#define B_SMEM   133376
// X1h @ B_XB, X1l @ B_XB+34816 ; H h @ B_XB, H l @ B_XB+18432 ; H3 @ B_XB+36864
// atom:
#define A_BIAS   0
#define A_XB     768      // activation region, 55296 B
#define A_WB     56064    // weight images, 54272 B
#define A_SMEM   110336

#define NT 256
#define TMROWS 128

// ================= phi_e over bonds =================
__global__ void __launch_bounds__(NT, 1) bond_kernel(
    const float* __restrict__ bonds, const int* __restrict__ ba1,
    const int* __restrict__ ba2, const float* __restrict__ atoms,
    const float* __restrict__ state,
    const float* __restrict__ eb1, const float* __restrict__ eb2,
    const float* __restrict__ eb3,
    float* __restrict__ out_bonds, int n_bonds)
{
    extern __shared__ char smem[];
    const int tid  = threadIdx.x;
    const int wid  = tid >> 5;
    const int lane = tid & 31;
    const int g = lane >> 2, t = lane & 3;
    const int wm = wid >> 1, wn = wid & 1;
    const int base = blockIdx.x * TMROWS;

    float* Bs  = (float*)(smem + B_BIAS);       // [0:64) b1, [64:128) b2, [128:160) b3
    int*   A1s = (int*)(smem + B_A1S);
    uint32_t* Xh = (uint32_t*)(smem + B_XB);
    uint32_t* Xl = (uint32_t*)(smem + B_XB + 34816);
    uint32_t* Hh = (uint32_t*)(smem + B_XB);
    uint32_t* Hl = (uint32_t*)(smem + B_XB + 18432);
    float*    H3 = (float*)(smem + B_XB + 36864);
    const uint32_t* W1h = (const uint32_t*)(smem + B_WB);
    const uint32_t* W1l = (const uint32_t*)(smem + B_WB + 17408);
    const uint32_t* W2h = (const uint32_t*)(smem + B_WB + 34816);
    const uint32_t* W2l = (const uint32_t*)(smem + B_WB + 44032);
    const uint32_t* W3h = (const uint32_t*)(smem + B_WB + 53248);
    const uint32_t* W3l = (const uint32_t*)(smem + B_WB + 57856);

    // weights -> smem (bulk copy, L2-hot)
    {
        const int4* src = (const int4*)g_we;
        int4* dst = (int4*)(smem + B_WB);
        for (int i = tid; i < 62464 / 16; i += NT) dst[i] = src[i];
    }
    if (tid < 64) { Bs[tid] = eb1[tid]; Bs[64 + tid] = eb2[tid]; }
    else if (tid < 96) Bs[128 + tid - 64] = eb3[tid - 64];

    // ---- stage X (128 rows x 128 cols): row m, half covers 64 cols ----
    {
        const int m = tid >> 1, half = tid & 1;
        const int gid = base + m;
        const int a1 = ba1[gid];
        float f[64];
        const float* s0;
        const float* s1;
        if (half == 0) {
            int a2 = ba2[gid];
            A1s[m] = a1;
            atomicAdd(&g_cnt[a1], 1.0f);
            s0 = atoms + (size_t)a1 * 32;
            s1 = atoms + (size_t)a2 * 32;
        } else {
            s0 = bonds + (size_t)gid * 32;
            s1 = state;
        }
#pragma unroll
        for (int q = 0; q < 8; q++) {
            float4 v = *(const float4*)(s0 + 4 * q);
            f[4 * q] = v.x; f[4 * q + 1] = v.y; f[4 * q + 2] = v.z; f[4 * q + 3] = v.w;
            float4 u = *(const float4*)(s1 + 4 * q);
            f[32 + 4 * q] = u.x; f[33 + 4 * q] = u.y; f[34 + 4 * q] = u.z; f[35 + 4 * q] = u.w;
        }
        const int wbase = m * 68 + half * 32;
#pragma unroll
        for (int p = 0; p < 32; p++) {
            uint32_t hw, lw;
            split_pair(f[2 * p], f[2 * p + 1], hw, lw);
            Xh[wbase + p] = hw;
            Xl[wbase + p] = lw;
        }
    }
    __syncthreads();

    // ---- layer 1: K=128 (saw=68), N=64 ----
    {
        float acc[2][4][4];
        mlp_layer<8, 4>(Xh, Xl, 68, W1h, W1l, 68, wm, wn, g, t, acc);
        __syncthreads();  // all reads of X done before overwrite
        epi_to_h<4>(acc, Bs, Hh, Hl, 36, wm, wn, g, t);
    }
    __syncthreads();

    // ---- layer 2: K=64 (saw=36), N=64 ----
    {
        float acc[2][4][4];
        mlp_layer<4, 4>(Hh, Hl, 36, W2h, W2l, 36, wm, wn, g, t, acc);
        __syncthreads();
        epi_to_h<4>(acc, Bs + 64, Hh, Hl, 36, wm, wn, g, t);
    }
    __syncthreads();

    // ---- layer 3: K=64, N=32 ----
    {
        float acc[2][2][4];
        mlp_layer<4, 2>(Hh, Hl, 36, W3h, W3l, 36, wm, wn, g, t, acc);
        epi_to_f32<2>(acc, Bs + 128, H3, wm, wn, g, t);
    }
    __syncthreads();

    // ---- outputs ----
    for (int idx = tid; idx < TMROWS * 8; idx += NT) {
        int r = idx >> 3, f4 = idx & 7;
        float4 v = *(float4*)&H3[r * 36 + (f4 << 2)];
        *(float4*)&out_bonds[(size_t)(base + r) * 32 + (f4 << 2)] = v;
    }
    for (int r = wid; r < TMROWS; r += 8)
        atomicAdd(&g_b2a[(size_t)A1s[r] * 32 + lane], H3[r * 36 + lane]);
    if (tid < 32) {
        float ssum = 0.f;
        for (int r = 0; r < TMROWS; r++) ssum += H3[r * 36 + tid];
        atomicAdd(&g_bsum[tid], ssum);
    }
}

// ================= phi_v over atoms =================
__global__ void __launch_bounds__(NT, 2) atom_kernel(
    const float* __restrict__ atoms, const float* __restrict__ state,
    const float* __restrict__ vb1, const float* __restrict__ vb2,
    const float* __restrict__ vb3,
    float* __restrict__ out_atoms, int n_atoms)
{
    extern __shared__ char smem[];
    const int tid  = threadIdx.x;
    const int wid  = tid >> 5;
    const int lane = tid & 31;
    const int g = lane >> 2, t = lane & 3;
    const int wm = wid >> 1, wn = wid & 1;
    const int base = blockIdx.x * TMROWS;

    float* Bs = (float*)(smem + A_BIAS);
    uint32_t* Xh = (uint32_t*)(smem + A_XB);
    uint32_t* Xl = (uint32_t*)(smem + A_XB + 26624);
    uint32_t* Hh = (uint32_t*)(smem + A_XB);
    uint32_t* Hl = (uint32_t*)(smem + A_XB + 18432);
    float*    H3 = (float*)(smem + A_XB + 36864);
    const uint32_t* V1h = (const uint32_t*)(smem + A_WB);
    const uint32_t* V1l = (const uint32_t*)(smem + A_WB + 13312);
    const uint32_t* V2h = (const uint32_t*)(smem + A_WB + 26624);
    const uint32_t* V2l = (const uint32_t*)(smem + A_WB + 35840);
    const uint32_t* V3h = (const uint32_t*)(smem + A_WB + 45056);
    const uint32_t* V3l = (const uint32_t*)(smem + A_WB + 49664);

    {
        const int4* src = (const int4*)g_wv;
        int4* dst = (int4*)(smem + A_WB);
        for (int i = tid; i < 54272 / 16; i += NT) dst[i] = src[i];
    }
    if (tid < 64) { Bs[tid] = vb1[tid]; Bs[64 + tid] = vb2[tid]; }
    else if (tid < 96) Bs[128 + tid - 64] = vb3[tid - 64];

    // ---- stage X (128 rows x 96 cols, saw=52): row m, half covers 48 cols ----
    {
        const int m = tid >> 1, half = tid & 1;
        const int gm = base + m;
        const int id = gm < n_atoms ? gm : n_atoms - 1;
        float f[48];
        if (half == 0) {
            float inv = 1.0f / g_cnt[id];
#pragma unroll
            for (int q = 0; q < 8; q++) {
                float4 v = *(const float4*)&g_b2a[(size_t)id * 32 + 4 * q];
                f[4 * q] = v.x * inv; f[4 * q + 1] = v.y * inv;
                f[4 * q + 2] = v.z * inv; f[4 * q + 3] = v.w * inv;
            }
#pragma unroll
            for (int q = 0; q < 4; q++) {
                float4 v = *(const float4*)&atoms[(size_t)id * 32 + 4 * q];
                f[32 + 4 * q] = v.x; f[33 + 4 * q] = v.y; f[34 + 4 * q] = v.z; f[35 + 4 * q] = v.w;
            }
        } else {
#pragma unroll
            for (int q = 0; q < 4; q++) {
                float4 v = *(const float4*)&atoms[(size_t)id * 32 + 16 + 4 * q];
                f[4 * q] = v.x; f[4 * q + 1] = v.y; f[4 * q + 2] = v.z; f[4 * q + 3] = v.w;
            }
#pragma unroll
            for (int q = 0; q < 8; q++) {
                float4 v = *(const float4*)&state[4 * q];
                f[16 + 4 * q] = v.x; f[17 + 4 * q] = v.y; f[18 + 4 * q] = v.z; f[19 + 4 * q] = v.w;
            }
        }
        const int wbase = m * 52 + half * 24;
#pragma unroll
        for (int p = 0; p < 24; p++) {
            uint32_t hw, lw;
            split_pair(f[2 * p], f[2 * p + 1], hw, lw);
            Xh[wbase + p] = hw;
            Xl[wbase + p] = lw;
        }
    }
    __syncthreads();

    // ---- layer 1: K=96 (saw=52), N=64 ----
    {
        float acc[2][4][4];
        mlp_layer<6, 4>(Xh, Xl, 52, V1h, V1l, 52, wm, wn, g, t, acc);
        __syncthreads();
        epi_to_h<4>(acc, Bs, Hh, Hl, 36, wm, wn, g, t);
    }
    __syncthreads();

    // ---- layer 2 ----
    {
        float acc[2][4][4];
        mlp_layer<4, 4>(Hh, Hl, 36, V2h, V2l, 36, wm, wn, g, t, acc);
        __syncthreads();
        epi_to_h<4>(acc, Bs + 64, Hh, Hl, 36, wm, wn, g, t);
    }
    __syncthreads();

    // ---- layer 3 ----
    {
        float acc[2][2][4];
        mlp_layer<4, 2>(Hh, Hl, 36, V3h, V3l, 36, wm, wn, g, t, acc);
        epi_to_f32<2>(acc, Bs + 128, H3, wm, wn, g, t);
    }
    __syncthreads();

    for (int idx = tid; idx < TMROWS * 8; idx += NT) {
        int r = idx >> 3, f4 = idx & 7;
        if (base + r < n_atoms) {
            float4 v = *(float4*)&H3[r * 36 + (f4 << 2)];
            *(float4*)&out_atoms[(size_t)(base + r) * 32 + (f4 << 2)] = v;
        }
    }
    if (tid < 32) {
        float ssum = 0.f;
        for (int r = 0; r < TMROWS; r++)
            if (base + r < n_atoms) ssum += H3[r * 36 + tid];
        atomicAdd(&g_asum[tid], ssum);
    }
}

// ================= phi_u =================
__global__ void state_kernel(
    const float* __restrict__ state,
    const float* __restrict__ uw1, const float* __restrict__ ub1,
    const float* __restrict__ uw2, const float* __restrict__ ub2,
    const float* __restrict__ uw3, const float* __restrict__ ub3,
    float* __restrict__ out_state, int n_bonds, int n_atoms)
{
    __shared__ float x[96], h1[64], h2[64];
    int tid = threadIdx.x;  // 64 threads
    if (tid < 32) {
        x[tid]      = g_bsum[tid] / (float)n_bonds;
        x[32 + tid] = g_asum[tid] / (float)n_atoms;
        x[64 + tid] = state[tid];
    }
    __syncthreads();
    {
        float a = ub1[tid];
        for (int k = 0; k < 96; k++) a = fmaf(x[k], uw1[k * 64 + tid], a);
        h1[tid] = selu_f(a);
    }
    __syncthreads();
    {
        float a = ub2[tid];
        for (int k = 0; k < 64; k++) a = fmaf(h1[k], uw2[k * 64 + tid], a);
        h2[tid] = selu_f(a);
    }
    __syncthreads();
    if (tid < 32) {
        float a = ub3[tid];
        for (int k = 0; k < 64; k++) a = fmaf(h2[k], uw3[k * 32 + tid], a);
        out_state[tid] = selu_f(a);
    }
}

// ================= launch =================
extern "C" void kernel_launch(void* const* d_in, const int* in_sizes, int n_in,
                              void* d_out, int out_size)
{
    const float* bonds = (const float*)d_in[0];
    const int*   ba1   = (const int*)d_in[1];
    const int*   ba2   = (const int*)d_in[2];
    const float* atoms = (const float*)d_in[3];
    const float* state = (const float*)d_in[4];
    const float* ew1 = (const float*)d_in[5];
    const float* eb1 = (const float*)d_in[6];
    const float* ew2 = (const float*)d_in[7];
    const float* eb2 = (const float*)d_in[8];
    const float* ew3 = (const float*)d_in[9];
    const float* eb3 = (const float*)d_in[10];
    const float* vw1 = (const float*)d_in[11];
    const float* vb1 = (const float*)d_in[12];
    const float* vw2 = (const float*)d_in[13];
    const float* vb2 = (const float*)d_in[14];
    const float* vw3 = (const float*)d_in[15];
    const float* vb3 = (const float*)d_in[16];
    const float* uw1 = (const float*)d_in[17];
    const float* ub1 = (const float*)d_in[18];
    const float* uw2 = (const float*)d_in[19];
    const float* ub2 = (const float*)d_in[20];
    const float* uw3 = (const float*)d_in[21];
    const float* ub3 = (const float*)d_in[22];

    const int n_bonds = in_sizes[1];
    const int n_atoms = in_sizes[3] / 32;

    float* out       = (float*)d_out;
    float* out_bonds = out;
    float* out_atoms = out + (size_t)n_bonds * 32;
    float* out_state = out_atoms + (size_t)n_atoms * 32;

    cudaFuncSetAttribute(bond_kernel, cudaFuncAttributeMaxDynamicSharedMemorySize, B_SMEM);
    cudaFuncSetAttribute(atom_kernel, cudaFuncAttributeMaxDynamicSharedMemorySize, A_SMEM);

    zero_kernel<<<256, 256>>>(n_atoms);
    prep_kernel<<<(29184 + 255) / 256, 256>>>(ew1, ew2, ew3, vw1, vw2, vw3);

    int bond_blocks = n_bonds / TMROWS;
    bond_kernel<<<bond_blocks, NT, B_SMEM>>>(
        bonds, ba1, ba2, atoms, state, eb1, eb2, eb3, out_bonds, n_bonds);

    int atom_blocks = (n_atoms + TMROWS - 1) / TMROWS;
    atom_kernel<<<atom_blocks, NT, A_SMEM>>>(
        atoms, state, vb1, vb2, vb3, out_atoms, n_atoms);

    state_kernel<<<1, 64>>>(state, uw1, ub1, uw2, ub2, uw3, ub3,
                            out_state, n_bonds, n_atoms);
}

// round 5
// speedup vs baseline: 2.8953x; 1.2520x over previous
#include <cuda_runtime.h>
#include <cuda_bf16.h>
#include <math.h>
#include <stdint.h>

// ================= scratch (no allocations allowed) =================
#define MAX_ATOMS 100000
__device__ float g_b2a[MAX_ATOMS * 32];
__device__ float g_cnt[MAX_ATOMS];
__device__ float g_bsum[32];
__device__ float g_asum[32];

// pre-transposed bf16 weight images Wt[n][k], hi/lo split, padded k-stride
__device__ __align__(16) __nv_bfloat16 g_we[31232];
__device__ __align__(16) __nv_bfloat16 g_wv[27136];

#define EW1H 0
#define EW1L 8704
#define EW2H 17408
#define EW2L 22016
#define EW3H 26624
#define EW3L 28928
#define VW1H 0
#define VW1L 6656
#define VW2H 13312
#define VW2L 17920
#define VW3H 22528
#define VW3L 24832

__device__ __forceinline__ float selu_f(float x) {
    const float lam = 1.0507009873554805f;
    const float la  = 1.7580993408473766f;
    return x > 0.f ? lam * x : la * expm1f(x);
}

__device__ __forceinline__ void split_pair(float v0, float v1, uint32_t& hw, uint32_t& lw) {
    __nv_bfloat16 h0 = __float2bfloat16(v0), h1 = __float2bfloat16(v1);
    __nv_bfloat162 hp; hp.x = h0; hp.y = h1;
    __nv_bfloat162 lp;
    lp.x = __float2bfloat16(v0 - __bfloat162float(h0));
    lp.y = __float2bfloat16(v1 - __bfloat162float(h1));
    hw = *(uint32_t*)&hp;
    lw = *(uint32_t*)&lp;
}

__device__ __forceinline__ uint32_t smem_u32(const void* p) {
    uint32_t a;
    asm("{ .reg .u64 t; cvta.to.shared.u64 t, %1; cvt.u32.u64 %0, t; }" : "=r"(a) : "l"(p));
    return a;
}

// ---- baseline-ISA tensor ops (valid on plain sm_100) ----
__device__ __forceinline__ void ldmx4(uint32_t r[4], uint32_t addr) {
    asm volatile("ldmatrix.sync.aligned.m8n8.x4.shared.b16 {%0,%1,%2,%3}, [%4];"
        : "=r"(r[0]), "=r"(r[1]), "=r"(r[2]), "=r"(r[3]) : "r"(addr));
}
__device__ __forceinline__ void mma_bf16(float c[4], const uint32_t a[4], uint32_t b0, uint32_t b1) {
    asm("mma.sync.aligned.m16n8k16.row.col.f32.bf16.bf16.f32 "
        "{%0,%1,%2,%3}, {%4,%5,%6,%7}, {%8,%9}, {%0,%1,%2,%3};"
        : "+f"(c[0]), "+f"(c[1]), "+f"(c[2]), "+f"(c[3])
        : "r"(a[0]), "r"(a[1]), "r"(a[2]), "r"(a[3]), "r"(b0), "r"(b1));
}

// one dense layer: acc[NTW][4] += A(16 rows x K) @ Wt^T  (3-pass bf16 split)
// addresses are lane-resolved smem byte addrs; sbwB = B image row stride bytes
template <int KS, int NTW>
__device__ __forceinline__ void mlp_layer(
    uint32_t xh_addr, uint32_t xl_addr,
    uint32_t bh_addr, uint32_t bl_addr, uint32_t sbwB,
    float acc[NTW][4])
{
#pragma unroll
    for (int j = 0; j < NTW; j++)
#pragma unroll
        for (int q = 0; q < 4; q++) acc[j][q] = 0.f;

#pragma unroll
    for (int k = 0; k < KS; k++) {
        uint32_t ah[4], al[4];
        ldmx4(ah, xh_addr);
        ldmx4(al, xl_addr);
        xh_addr += 32; xl_addr += 32;
#pragma unroll
        for (int p = 0; p < NTW / 2; p++) {
            uint32_t rh[4], rl[4];
            ldmx4(rh, bh_addr + p * 8 * sbwB * 2);
            ldmx4(rl, bl_addr + p * 8 * sbwB * 2);
            mma_bf16(acc[2 * p],     ah, rh[0], rh[1]);
            mma_bf16(acc[2 * p + 1], ah, rh[2], rh[3]);
            mma_bf16(acc[2 * p],     ah, rl[0], rl[1]);
            mma_bf16(acc[2 * p + 1], ah, rl[2], rl[3]);
            mma_bf16(acc[2 * p],     al, rh[0], rh[1]);
            mma_bf16(acc[2 * p + 1], al, rh[2], rh[3]);
        }
        bh_addr += 32; bl_addr += 32;
    }
}

// epilogue: bias+selu -> split -> bf16 H images (stride 36 words)
template <int NTW>
__device__ __forceinline__ void epi_to_h(
    float acc[NTW][4], const float* bias,
    uint32_t* Hh, uint32_t* Hl, int wm, int wn, int g, int t)
{
    const int r0 = wm * 16 + g;
#pragma unroll
    for (int j = 0; j < NTW; j++) {
        int col = wn * 32 + j * 8 + 2 * t;
        int cw  = wn * 16 + j * 4 + t;
        float b0 = bias[col], b1 = bias[col + 1];
        uint32_t hw, lw;
        split_pair(selu_f(acc[j][0] + b0), selu_f(acc[j][1] + b1), hw, lw);
        Hh[r0 * 36 + cw] = hw; Hl[r0 * 36 + cw] = lw;
        split_pair(selu_f(acc[j][2] + b0), selu_f(acc[j][3] + b1), hw, lw);
        Hh[(r0 + 8) * 36 + cw] = hw; Hl[(r0 + 8) * 36 + cw] = lw;
    }
}

// epilogue: bias+selu -> fp32 H3 staging [128][36]  (N=32, NTW=2)
__device__ __forceinline__ void epi_to_f32(
    float acc[2][4], const float* bias, float* H3, int wm, int wn, int g, int t)
{
    const int r0 = wm * 16 + g;
#pragma unroll
    for (int j = 0; j < 2; j++) {
        int col = wn * 16 + j * 8 + 2 * t;
        float b0 = bias[col], b1 = bias[col + 1];
        float2 v;
        v.x = selu_f(acc[j][0] + b0);
        v.y = selu_f(acc[j][1] + b1);
        *(float2*)&H3[r0 * 36 + col] = v;
        v.x = selu_f(acc[j][2] + b0);
        v.y = selu_f(acc[j][3] + b1);
        *(float2*)&H3[(r0 + 8) * 36 + col] = v;
    }
}

// ================= zero scratch =================
__global__ void zero_kernel(int n_atoms)
{
    int i = blockIdx.x * blockDim.x + threadIdx.x;
    int stride = gridDim.x * blockDim.x;
    int nb = n_atoms * 32;
    for (int idx = i; idx < nb; idx += stride) g_b2a[idx] = 0.f;
    for (int idx = i; idx < n_atoms; idx += stride) g_cnt[idx] = 0.f;
    if (i < 32) { g_bsum[i] = 0.f; g_asum[i] = 0.f; }
}

// ================= weight transpose + split prep =================
__global__ void prep_kernel(
    const float* __restrict__ ew1, const float* __restrict__ ew2, const float* __restrict__ ew3,
    const float* __restrict__ vw1, const float* __restrict__ vw2, const float* __restrict__ vw3)
{
    int i = blockIdx.x * blockDim.x + threadIdx.x;
    if (i >= 29184) return;
    const float* src; __nv_bfloat16 *ih, *il;
    int stride, N, Ksrc, local;
    if (i < 8704)        { local = i;         stride = 136; N = 64; Ksrc = 128; src = ew1; ih = g_we + EW1H; il = g_we + EW1L; }
    else if (i < 13312)  { local = i - 8704;  stride = 72;  N = 64; Ksrc = 64;  src = ew2; ih = g_we + EW2H; il = g_we + EW2L; }
    else if (i < 15616)  { local = i - 13312; stride = 72;  N = 32; Ksrc = 64;  src = ew3; ih = g_we + EW3H; il = g_we + EW3L; }
    else if (i < 22272)  { local = i - 15616; stride = 104; N = 64; Ksrc = 96;  src = vw1; ih = g_wv + VW1H; il = g_wv + VW1L; }
    else if (i < 26880)  { local = i - 22272; stride = 72;  N = 64; Ksrc = 64;  src = vw2; ih = g_wv + VW2H; il = g_wv + VW2L; }
    else                 { local = i - 26880; stride = 72;  N = 32; Ksrc = 64;  src = vw3; ih = g_wv + VW3H; il = g_wv + VW3L; }
    int n = local / stride, k = local % stride;
    float w = (k < Ksrc) ? src[k * N + n] : 0.f;
    __nv_bfloat16 h = __float2bfloat16(w);
    __nv_bfloat16 l = __float2bfloat16(w - __bfloat162float(h));
    ih[local] = h;
    il[local] = l;
}

// ================= smem maps (bytes) =================
#define B_BIAS   0
#define B_A1S    640
#define B_XB     1280
#define B_WB     70912
#define B_SMEM   133376
#define A_BIAS   0
#define A_XB     768
#define A_WB     56064
#define A_SMEM   110336

#define NT 512
#define TMROWS 128

// ================= phi_e over bonds =================
__global__ void __launch_bounds__(NT, 1) bond_kernel(
    const float* __restrict__ bonds, const int* __restrict__ ba1,
    const int* __restrict__ ba2, const float* __restrict__ atoms,
    const float* __restrict__ state,
    const float* __restrict__ eb1, const float* __restrict__ eb2,
    const float* __restrict__ eb3,
    float* __restrict__ out_bonds, int n_bonds)
{
    extern __shared__ char smem[];
    const uint32_t sb = smem_u32(smem);
    const int tid  = threadIdx.x;
    const int wid  = tid >> 5;
    const int lane = tid & 31;
    const int g = lane >> 2, t = lane & 3;
    const int wm = wid >> 1, wn = wid & 1;   // 8 m-tiles x 2 n-tiles
    const int base = blockIdx.x * TMROWS;

    float* Bs  = (float*)(smem + B_BIAS);
    int*   A1s = (int*)(smem + B_A1S);
    uint32_t* Xh = (uint32_t*)(smem + B_XB);
    uint32_t* Xl = (uint32_t*)(smem + B_XB + 34816);
    uint32_t* Hh = (uint32_t*)(smem + B_XB);
    uint32_t* Hl = (uint32_t*)(smem + B_XB + 18432);
    float*    H3 = (float*)(smem + B_XB + 36864);

    // weights -> smem (bulk copy, L2-hot)
    {
        const int4* src = (const int4*)g_we;
        int4* dst = (int4*)(smem + B_WB);
        for (int i = tid; i < 62464 / 16; i += NT) dst[i] = src[i];
    }
    if (tid < 64) { Bs[tid] = eb1[tid]; Bs[64 + tid] = eb2[tid]; }
    else if (tid < 96) Bs[128 + tid - 64] = eb3[tid - 64];

    // ---- stage X: 128 rows x 4 quarters of 32 elems ----
    {
        const int m = tid >> 2, q = tid & 3;
        const int gid = base + m;
        const float* src;
        if (q == 0) {
            int a1 = ba1[gid];
            A1s[m] = a1;
            atomicAdd(&g_cnt[a1], 1.0f);
            src = atoms + (size_t)a1 * 32;
        } else if (q == 1) {
            src = atoms + (size_t)ba2[gid] * 32;
        } else if (q == 2) {
            src = bonds + (size_t)gid * 32;
        } else {
            src = state;
        }
        float f[32];
#pragma unroll
        for (int p = 0; p < 8; p++) {
            float4 v = *(const float4*)(src + 4 * p);
            f[4 * p] = v.x; f[4 * p + 1] = v.y; f[4 * p + 2] = v.z; f[4 * p + 3] = v.w;
        }
        const int wbase = m * 68 + q * 16;
#pragma unroll
        for (int p = 0; p < 16; p++) {
            uint32_t hw, lw;
            split_pair(f[2 * p], f[2 * p + 1], hw, lw);
            Xh[wbase + p] = hw;
            Xl[wbase + p] = lw;
        }
    }
    __syncthreads();

    // lane-resolved fragment addresses
    const uint32_t a_row = (uint32_t)(wm * 16 + (lane & 15));
    const uint32_t a_kb  = (uint32_t)((lane >> 4) << 4);
    const uint32_t b_row = (uint32_t)(((lane >> 4) << 3) + (lane & 7));
    const uint32_t b_kb  = (uint32_t)(((lane >> 3) & 1) << 4);

    // ---- layer 1: K=128 (A stride 272B), W1 stride 272B, N=64 ----
    {
        float acc[4][4];
        uint32_t ao = a_row * 272 + a_kb;
        uint32_t bo = (wn * 32 + b_row) * 272 + b_kb;
        mlp_layer<8, 4>(sb + B_XB + ao, sb + B_XB + 34816 + ao,
                        sb + B_WB + bo, sb + B_WB + 17408 + bo, 272, acc);
        __syncthreads();  // all reads of X done before H overwrites it
        epi_to_h<4>(acc, Bs, Hh, Hl, wm, wn, g, t);
    }
    __syncthreads();

    // ---- layer 2: K=64 (A stride 144B), W2 stride 144B, N=64 ----
    {
        float acc[4][4];
        uint32_t ao = a_row * 144 + a_kb;
        uint32_t bo = (wn * 32 + b_row) * 144 + b_kb;
        mlp_layer<4, 4>(sb + B_XB + ao, sb + B_XB + 18432 + ao,
                        sb + B_WB + 34816 + bo, sb + B_WB + 44032 + bo, 144, acc);
        __syncthreads();
        epi_to_h<4>(acc, Bs + 64, Hh, Hl, wm, wn, g, t);
    }
    __syncthreads();

    // ---- layer 3: K=64, N=32, W3 stride 144B ----
    {
        float acc[2][4];
        uint32_t ao = a_row * 144 + a_kb;
        uint32_t bo = (wn * 16 + b_row) * 144 + b_kb;
        mlp_layer<4, 2>(sb + B_XB + ao, sb + B_XB + 18432 + ao,
                        sb + B_WB + 53248 + bo, sb + B_WB + 57856 + bo, 144, acc);
        epi_to_f32(acc, Bs + 128, H3, wm, wn, g, t);
    }
    __syncthreads();

    // ---- outputs ----
    for (int idx = tid; idx < TMROWS * 8; idx += NT) {
        int r = idx >> 3, f4 = idx & 7;
        float4 v = *(float4*)&H3[r * 36 + (f4 << 2)];
        *(float4*)&out_bonds[(size_t)(base + r) * 32 + (f4 << 2)] = v;
    }
    for (int r = wid; r < TMROWS; r += 16)
        atomicAdd(&g_b2a[(size_t)A1s[r] * 32 + lane], H3[r * 36 + lane]);
    if (tid < 32) {
        float ssum = 0.f;
        for (int r = 0; r < TMROWS; r++) ssum += H3[r * 36 + tid];
        atomicAdd(&g_bsum[tid], ssum);
    }
}

// ================= phi_v over atoms =================
__global__ void __launch_bounds__(NT, 1) atom_kernel(
    const float* __restrict__ atoms, const float* __restrict__ state,
    const float* __restrict__ vb1, const float* __restrict__ vb2,
    const float* __restrict__ vb3,
    float* __restrict__ out_atoms, int n_atoms)
{
    extern __shared__ char smem[];
    const uint32_t sb = smem_u32(smem);
    const int tid  = threadIdx.x;
    const int wid  = tid >> 5;
    const int lane = tid & 31;
    const int g = lane >> 2, t = lane & 3;
    const int wm = wid >> 1, wn = wid & 1;
    const int base = blockIdx.x * TMROWS;

    float* Bs = (float*)(smem + A_BIAS);
    uint32_t* Xh = (uint32_t*)(smem + A_XB);
    uint32_t* Xl = (uint32_t*)(smem + A_XB + 26624);
    uint32_t* Hh = (uint32_t*)(smem + A_XB);
    uint32_t* Hl = (uint32_t*)(smem + A_XB + 18432);
    float*    H3 = (float*)(smem + A_XB + 36864);

    {
        const int4* src = (const int4*)g_wv;
        int4* dst = (int4*)(smem + A_WB);
        for (int i = tid; i < 54272 / 16; i += NT) dst[i] = src[i];
    }
    if (tid < 64) { Bs[tid] = vb1[tid]; Bs[64 + tid] = vb2[tid]; }
    else if (tid < 96) Bs[128 + tid - 64] = vb3[tid - 64];

    // ---- stage X: 128 rows x 3 thirds of 32 elems (quarter 3 idle) ----
    {
        const int m = tid >> 2, q = tid & 3;
        if (q < 3) {
            const int gm = base + m;
            const int id = gm < n_atoms ? gm : n_atoms - 1;
            float f[32];
            if (q == 0) {
                float inv = 1.0f / g_cnt[id];
#pragma unroll
                for (int p = 0; p < 8; p++) {
                    float4 v = *(const float4*)&g_b2a[(size_t)id * 32 + 4 * p];
                    f[4 * p] = v.x * inv; f[4 * p + 1] = v.y * inv;
                    f[4 * p + 2] = v.z * inv; f[4 * p + 3] = v.w * inv;
                }
            } else {
                const float* src = (q == 1) ? atoms + (size_t)id * 32 : state;
#pragma unroll
                for (int p = 0; p < 8; p++) {
                    float4 v = *(const float4*)(src + 4 * p);
                    f[4 * p] = v.x; f[4 * p + 1] = v.y; f[4 * p + 2] = v.z; f[4 * p + 3] = v.w;
                }
            }
            const int wbase = m * 52 + q * 16;
#pragma unroll
            for (int p = 0; p < 16; p++) {
                uint32_t hw, lw;
                split_pair(f[2 * p], f[2 * p + 1], hw, lw);
                Xh[wbase + p] = hw;
                Xl[wbase + p] = lw;
            }
        }
    }
    __syncthreads();

    const uint32_t a_row = (uint32_t)(wm * 16 + (lane & 15));
    const uint32_t a_kb  = (uint32_t)((lane >> 4) << 4);
    const uint32_t b_row = (uint32_t)(((lane >> 4) << 3) + (lane & 7));
    const uint32_t b_kb  = (uint32_t)(((lane >> 3) & 1) << 4);

    // ---- layer 1: K=96 (A stride 208B), V1 stride 208B ----
    {
        float acc[4][4];
        uint32_t ao = a_row * 208 + a_kb;
        uint32_t bo = (wn * 32 + b_row) * 208 + b_kb;
        mlp_layer<6, 4>(sb + A_XB + ao, sb + A_XB + 26624 + ao,
                        sb + A_WB + bo, sb + A_WB + 13312 + bo, 208, acc);
        __syncthreads();
        epi_to_h<4>(acc, Bs, Hh, Hl, wm, wn, g, t);
    }
    __syncthreads();

    // ---- layer 2 ----
    {
        float acc[4][4];
        uint32_t ao = a_row * 144 + a_kb;
        uint32_t bo = (wn * 32 + b_row) * 144 + b_kb;
        mlp_layer<4, 4>(sb + A_XB + ao, sb + A_XB + 18432 + ao,
                        sb + A_WB + 26624 + bo, sb + A_WB + 35840 + bo, 144, acc);
        __syncthreads();
        epi_to_h<4>(acc, Bs + 64, Hh, Hl, wm, wn, g, t);
    }
    __syncthreads();

    // ---- layer 3 ----
    {
        float acc[2][4];
        uint32_t ao = a_row * 144 + a_kb;
        uint32_t bo = (wn * 16 + b_row) * 144 + b_kb;
        mlp_layer<4, 2>(sb + A_XB + ao, sb + A_XB + 18432 + ao,
                        sb + A_WB + 45056 + bo, sb + A_WB + 49664 + bo, 144, acc);
        epi_to_f32(acc, Bs + 128, H3, wm, wn, g, t);
    }
    __syncthreads();

    for (int idx = tid; idx < TMROWS * 8; idx += NT) {
        int r = idx >> 3, f4 = idx & 7;
        if (base + r < n_atoms) {
            float4 v = *(float4*)&H3[r * 36 + (f4 << 2)];
            *(float4*)&out_atoms[(size_t)(base + r) * 32 + (f4 << 2)] = v;
        }
    }
    if (tid < 32) {
        float ssum = 0.f;
        for (int r = 0; r < TMROWS; r++)
            if (base + r < n_atoms) ssum += H3[r * 36 + tid];
        atomicAdd(&g_asum[tid], ssum);
    }
}

// ================= phi_u =================
__global__ void state_kernel(
    const float* __restrict__ state,
    const float* __restrict__ uw1, const float* __restrict__ ub1,
    const float* __restrict__ uw2, const float* __restrict__ ub2,
    const float* __restrict__ uw3, const float* __restrict__ ub3,
    float* __restrict__ out_state, int n_bonds, int n_atoms)
{
    __shared__ float x[96], h1[64], h2[64];
    int tid = threadIdx.x;  // 64 threads
    if (tid < 32) {
        x[tid]      = g_bsum[tid] / (float)n_bonds;
        x[32 + tid] = g_asum[tid] / (float)n_atoms;
        x[64 + tid] = state[tid];
    }
    __syncthreads();
    {
        float a = ub1[tid];
        for (int k = 0; k < 96; k++) a = fmaf(x[k], uw1[k * 64 + tid], a);
        h1[tid] = selu_f(a);
    }
    __syncthreads();
    {
        float a = ub2[tid];
        for (int k = 0; k < 64; k++) a = fmaf(h1[k], uw2[k * 64 + tid], a);
        h2[tid] = selu_f(a);
    }
    __syncthreads();
    if (tid < 32) {
        float a = ub3[tid];
        for (int k = 0; k < 64; k++) a = fmaf(h2[k], uw3[k * 32 + tid], a);
        out_state[tid] = selu_f(a);
    }
}

// ================= launch =================
extern "C" void kernel_launch(void* const* d_in, const int* in_sizes, int n_in,
                              void* d_out, int out_size)
{
    const float* bonds = (const float*)d_in[0];
    const int*   ba1   = (const int*)d_in[1];
    const int*   ba2   = (const int*)d_in[2];
    const float* atoms = (const float*)d_in[3];
    const float* state = (const float*)d_in[4];
    const float* ew1 = (const float*)d_in[5];
    const float* eb1 = (const float*)d_in[6];
    const float* ew2 = (const float*)d_in[7];
    const float* eb2 = (const float*)d_in[8];
    const float* ew3 = (const float*)d_in[9];
    const float* eb3 = (const float*)d_in[10];
    const float* vw1 = (const float*)d_in[11];
    const float* vb1 = (const float*)d_in[12];
    const float* vw2 = (const float*)d_in[13];
    const float* vb2 = (const float*)d_in[14];
    const float* vw3 = (const float*)d_in[15];
    const float* vb3 = (const float*)d_in[16];
    const float* uw1 = (const float*)d_in[17];
    const float* ub1 = (const float*)d_in[18];
    const float* uw2 = (const float*)d_in[19];
    const float* ub2 = (const float*)d_in[20];
    const float* uw3 = (const float*)d_in[21];
    const float* ub3 = (const float*)d_in[22];

    const int n_bonds = in_sizes[1];
    const int n_atoms = in_sizes[3] / 32;

    float* out       = (float*)d_out;
    float* out_bonds = out;
    float* out_atoms = out + (size_t)n_bonds * 32;
    float* out_state = out_atoms + (size_t)n_atoms * 32;

    cudaFuncSetAttribute(bond_kernel, cudaFuncAttributeMaxDynamicSharedMemorySize, B_SMEM);
    cudaFuncSetAttribute(atom_kernel, cudaFuncAttributeMaxDynamicSharedMemorySize, A_SMEM);

    zero_kernel<<<256, 256>>>(n_atoms);
    prep_kernel<<<(29184 + 255) / 256, 256>>>(ew1, ew2, ew3, vw1, vw2, vw3);

    int bond_blocks = n_bonds / TMROWS;
    bond_kernel<<<bond_blocks, NT, B_SMEM>>>(
        bonds, ba1, ba2, atoms, state, eb1, eb2, eb3, out_bonds, n_bonds);

    int atom_blocks = (n_atoms + TMROWS - 1) / TMROWS;
    atom_kernel<<<atom_blocks, NT, A_SMEM>>>(
        atoms, state, vb1, vb2, vb3, out_atoms, n_atoms);

    state_kernel<<<1, 64>>>(state, uw1, ub1, uw2, ub2, uw3, ub3,
                            out_state, n_bonds, n_atoms);
}

// round 6
// speedup vs baseline: 3.2363x; 1.1178x over previous
#include <cuda_runtime.h>
#include <cuda_bf16.h>
#include <math.h>
#include <stdint.h>

// ================= scratch (no allocations allowed) =================
#define MAX_ATOMS 100000
__device__ float g_b2a[MAX_ATOMS * 32];
__device__ float g_cnt[MAX_ATOMS];
__device__ float g_bsum[32];
__device__ float g_asum[32];

// pre-transposed bf16 weight images Wt[n][k], hi/lo split, padded k-stride
__device__ __align__(16) __nv_bfloat16 g_we[31232];
__device__ __align__(16) __nv_bfloat16 g_wv[27136];

#define EW1H 0
#define EW1L 8704
#define EW2H 17408
#define EW2L 22016
#define EW3H 26624
#define EW3L 28928
#define VW1H 0
#define VW1L 6656
#define VW2H 13312
#define VW2L 17920
#define VW3H 22528
#define VW3L 24832

__device__ __forceinline__ float selu_f(float x) {
    const float lam = 1.0507009873554805f;
    const float la  = 1.7580993408473766f;
    // fast path: MUFU-based exp (accuracy ~2^-22, far below bf16-split error)
    float e = __expf(x);
    return x > 0.f ? lam * x : fmaf(la, e, -la);
}

__device__ __forceinline__ void split_pair(float v0, float v1, uint32_t& hw, uint32_t& lw) {
    __nv_bfloat16 h0 = __float2bfloat16(v0), h1 = __float2bfloat16(v1);
    __nv_bfloat162 hp; hp.x = h0; hp.y = h1;
    __nv_bfloat162 lp;
    lp.x = __float2bfloat16(v0 - __bfloat162float(h0));
    lp.y = __float2bfloat16(v1 - __bfloat162float(h1));
    hw = *(uint32_t*)&hp;
    lw = *(uint32_t*)&lp;
}

__device__ __forceinline__ uint32_t smem_u32(const void* p) {
    uint32_t a;
    asm("{ .reg .u64 t; cvta.to.shared.u64 t, %1; cvt.u32.u64 %0, t; }" : "=r"(a) : "l"(p));
    return a;
}

// ---- baseline-ISA tensor ops (valid on plain sm_100) ----
__device__ __forceinline__ void ldmx4(uint32_t r[4], uint32_t addr) {
    asm volatile("ldmatrix.sync.aligned.m8n8.x4.shared.b16 {%0,%1,%2,%3}, [%4];"
        : "=r"(r[0]), "=r"(r[1]), "=r"(r[2]), "=r"(r[3]) : "r"(addr));
}
__device__ __forceinline__ void mma_bf16(float c[4], const uint32_t a[4], uint32_t b0, uint32_t b1) {
    asm("mma.sync.aligned.m16n8k16.row.col.f32.bf16.bf16.f32 "
        "{%0,%1,%2,%3}, {%4,%5,%6,%7}, {%8,%9}, {%0,%1,%2,%3};"
        : "+f"(c[0]), "+f"(c[1]), "+f"(c[2]), "+f"(c[3])
        : "r"(a[0]), "r"(a[1]), "r"(a[2]), "r"(a[3]), "r"(b0), "r"(b1));
}

// one dense layer: acc[NTW][4] += A(16 rows x K) @ Wt^T  (3-pass bf16 split)
template <int KS, int NTW>
__device__ __forceinline__ void mlp_layer(
    uint32_t xh_addr, uint32_t xl_addr,
    uint32_t bh_addr, uint32_t bl_addr, uint32_t sbwB,
    float acc[NTW][4])
{
#pragma unroll
    for (int j = 0; j < NTW; j++)
#pragma unroll
        for (int q = 0; q < 4; q++) acc[j][q] = 0.f;

#pragma unroll
    for (int k = 0; k < KS; k++) {
        uint32_t ah[4], al[4];
        ldmx4(ah, xh_addr);
        ldmx4(al, xl_addr);
        xh_addr += 32; xl_addr += 32;
#pragma unroll
        for (int p = 0; p < NTW / 2; p++) {
            uint32_t rh[4], rl[4];
            ldmx4(rh, bh_addr + p * 8 * sbwB * 2);
            ldmx4(rl, bl_addr + p * 8 * sbwB * 2);
            mma_bf16(acc[2 * p],     ah, rh[0], rh[1]);
            mma_bf16(acc[2 * p + 1], ah, rh[2], rh[3]);
            mma_bf16(acc[2 * p],     ah, rl[0], rl[1]);
            mma_bf16(acc[2 * p + 1], ah, rl[2], rl[3]);
            mma_bf16(acc[2 * p],     al, rh[0], rh[1]);
            mma_bf16(acc[2 * p + 1], al, rh[2], rh[3]);
        }
        bh_addr += 32; bl_addr += 32;
    }
}

// epilogue: bias+selu -> split -> bf16 H images (stride 36 words)
template <int NTW>
__device__ __forceinline__ void epi_to_h(
    float acc[NTW][4], const float* bias,
    uint32_t* Hh, uint32_t* Hl, int wm, int wn, int g, int t)
{
    const int r0 = wm * 16 + g;
#pragma unroll
    for (int j = 0; j < NTW; j++) {
        int col = wn * 32 + j * 8 + 2 * t;
        int cw  = wn * 16 + j * 4 + t;
        float b0 = bias[col], b1 = bias[col + 1];
        uint32_t hw, lw;
        split_pair(selu_f(acc[j][0] + b0), selu_f(acc[j][1] + b1), hw, lw);
        Hh[r0 * 36 + cw] = hw; Hl[r0 * 36 + cw] = lw;
        split_pair(selu_f(acc[j][2] + b0), selu_f(acc[j][3] + b1), hw, lw);
        Hh[(r0 + 8) * 36 + cw] = hw; Hl[(r0 + 8) * 36 + cw] = lw;
    }
}

// epilogue: bias+selu -> fp32 H3 staging [rows][36]  (N=32, NTW=2)
__device__ __forceinline__ void epi_to_f32(
    float acc[2][4], const float* bias, float* H3, int wm, int wn, int g, int t)
{
    const int r0 = wm * 16 + g;
#pragma unroll
    for (int j = 0; j < 2; j++) {
        int col = wn * 16 + j * 8 + 2 * t;
        float b0 = bias[col], b1 = bias[col + 1];
        float2 v;
        v.x = selu_f(acc[j][0] + b0);
        v.y = selu_f(acc[j][1] + b1);
        *(float2*)&H3[r0 * 36 + col] = v;
        v.x = selu_f(acc[j][2] + b0);
        v.y = selu_f(acc[j][3] + b1);
        *(float2*)&H3[(r0 + 8) * 36 + col] = v;
    }
}

// ================= zero scratch =================
__global__ void zero_kernel(int n_atoms)
{
    int i = blockIdx.x * blockDim.x + threadIdx.x;
    int stride = gridDim.x * blockDim.x;
    int nb = n_atoms * 32;
    for (int idx = i; idx < nb; idx += stride) g_b2a[idx] = 0.f;
    for (int idx = i; idx < n_atoms; idx += stride) g_cnt[idx] = 0.f;
    if (i < 32) { g_bsum[i] = 0.f; g_asum[i] = 0.f; }
}

// ================= weight transpose + split prep =================
__global__ void prep_kernel(
    const float* __restrict__ ew1, const float* __restrict__ ew2, const float* __restrict__ ew3,
    const float* __restrict__ vw1, const float* __restrict__ vw2, const float* __restrict__ vw3)
{
    int i = blockIdx.x * blockDim.x + threadIdx.x;
    if (i >= 29184) return;
    const float* src; __nv_bfloat16 *ih, *il;
    int stride, N, Ksrc, local;
    if (i < 8704)        { local = i;         stride = 136; N = 64; Ksrc = 128; src = ew1; ih = g_we + EW1H; il = g_we + EW1L; }
    else if (i < 13312)  { local = i - 8704;  stride = 72;  N = 64; Ksrc = 64;  src = ew2; ih = g_we + EW2H; il = g_we + EW2L; }
    else if (i < 15616)  { local = i - 13312; stride = 72;  N = 32; Ksrc = 64;  src = ew3; ih = g_we + EW3H; il = g_we + EW3L; }
    else if (i < 22272)  { local = i - 15616; stride = 104; N = 64; Ksrc = 96;  src = vw1; ih = g_wv + VW1H; il = g_wv + VW1L; }
    else if (i < 26880)  { local = i - 22272; stride = 72;  N = 64; Ksrc = 64;  src = vw2; ih = g_wv + VW2H; il = g_wv + VW2L; }
    else                 { local = i - 26880; stride = 72;  N = 32; Ksrc = 64;  src = vw3; ih = g_wv + VW3H; il = g_wv + VW3L; }
    int n = local / stride, k = local % stride;
    float w = (k < Ksrc) ? src[k * N + n] : 0.f;
    __nv_bfloat16 h = __float2bfloat16(w);
    __nv_bfloat16 l = __float2bfloat16(w - __bfloat162float(h));
    ih[local] = h;
    il[local] = l;
}

// ================= smem maps (bytes) =================
// bond: TMROWS=64 -> Xh 17408, Xl 17408; H 9216 hi + 9216 lo overlay; H3 9216 @ +18432
#define B_BIAS   0
#define B_A1S    640
#define B_XB     1024
#define B_WB     35840
#define B_SMEM   98304
// atom: Xh 13312, Xl 13312 (region 27648 to fit H3 @ +18432)
#define A_BIAS   0
#define A_XB     768
#define A_WB     28416
#define A_SMEM   82688

#define NT 256
#define TMROWS 64

// ================= phi_e over bonds =================
__global__ void __launch_bounds__(NT, 2) bond_kernel(
    const float* __restrict__ bonds, const int* __restrict__ ba1,
    const int* __restrict__ ba2, const float* __restrict__ atoms,
    const float* __restrict__ state,
    const float* __restrict__ eb1, const float* __restrict__ eb2,
    const float* __restrict__ eb3,
    float* __restrict__ out_bonds, int n_bonds)
{
    extern __shared__ char smem[];
    const uint32_t sb = smem_u32(smem);
    const int tid  = threadIdx.x;
    const int wid  = tid >> 5;
    const int lane = tid & 31;
    const int g = lane >> 2, t = lane & 3;
    const int wm = wid >> 1, wn = wid & 1;   // 4 m-tiles x 2 n-tiles
    const int base = blockIdx.x * TMROWS;

    float* Bs  = (float*)(smem + B_BIAS);
    int*   A1s = (int*)(smem + B_A1S);
    uint32_t* Xh = (uint32_t*)(smem + B_XB);
    uint32_t* Xl = (uint32_t*)(smem + B_XB + 17408);
    uint32_t* Hh = (uint32_t*)(smem + B_XB);
    uint32_t* Hl = (uint32_t*)(smem + B_XB + 9216);
    float*    H3 = (float*)(smem + B_XB + 18432);

    // weights -> smem (bulk copy, L2-hot)
    {
        const int4* src = (const int4*)g_we;
        int4* dst = (int4*)(smem + B_WB);
        for (int i = tid; i < 62464 / 16; i += NT) dst[i] = src[i];
    }
    if (tid < 64) { Bs[tid] = eb1[tid]; Bs[64 + tid] = eb2[tid]; }
    else if (tid < 96) Bs[128 + tid - 64] = eb3[tid - 64];

    // ---- stage X: 64 rows x 4 quarters of 32 elems ----
    {
        const int m = tid >> 2, q = tid & 3;
        const int gid = base + m;
        const float* src;
        if (q == 0) {
            int a1 = ba1[gid];
            A1s[m] = a1;
            atomicAdd(&g_cnt[a1], 1.0f);
            src = atoms + (size_t)a1 * 32;
        } else if (q == 1) {
            src = atoms + (size_t)ba2[gid] * 32;
        } else if (q == 2) {
            src = bonds + (size_t)gid * 32;
        } else {
            src = state;
        }
        float f[32];
#pragma unroll
        for (int p = 0; p < 8; p++) {
            float4 v = *(const float4*)(src + 4 * p);
            f[4 * p] = v.x; f[4 * p + 1] = v.y; f[4 * p + 2] = v.z; f[4 * p + 3] = v.w;
        }
        const int wbase = m * 68 + q * 16;
#pragma unroll
        for (int p = 0; p < 16; p++) {
            uint32_t hw, lw;
            split_pair(f[2 * p], f[2 * p + 1], hw, lw);
            Xh[wbase + p] = hw;
            Xl[wbase + p] = lw;
        }
    }
    __syncthreads();

    // lane-resolved fragment addresses
    const uint32_t a_row = (uint32_t)(wm * 16 + (lane & 15));
    const uint32_t a_kb  = (uint32_t)((lane >> 4) << 4);
    const uint32_t b_row = (uint32_t)(((lane >> 4) << 3) + (lane & 7));
    const uint32_t b_kb  = (uint32_t)(((lane >> 3) & 1) << 4);

    // ---- layer 1: K=128 (A stride 272B), W1 stride 272B, N=64 ----
    {
        float acc[4][4];
        uint32_t ao = a_row * 272 + a_kb;
        uint32_t bo = (wn * 32 + b_row) * 272 + b_kb;
        mlp_layer<8, 4>(sb + B_XB + ao, sb + B_XB + 17408 + ao,
                        sb + B_WB + bo, sb + B_WB + 17408 + bo, 272, acc);
        __syncthreads();  // all reads of X done before H overwrites it
        epi_to_h<4>(acc, Bs, Hh, Hl, wm, wn, g, t);
    }
    __syncthreads();

    // ---- layer 2: K=64 (A stride 144B), W2 stride 144B, N=64 ----
    {
        float acc[4][4];
        uint32_t ao = a_row * 144 + a_kb;
        uint32_t bo = (wn * 32 + b_row) * 144 + b_kb;
        mlp_layer<4, 4>(sb + B_XB + ao, sb + B_XB + 9216 + ao,
                        sb + B_WB + 34816 + bo, sb + B_WB + 44032 + bo, 144, acc);
        __syncthreads();
        epi_to_h<4>(acc, Bs + 64, Hh, Hl, wm, wn, g, t);
    }
    __syncthreads();

    // ---- layer 3: K=64, N=32, W3 stride 144B ----
    {
        float acc[2][4];
        uint32_t ao = a_row * 144 + a_kb;
        uint32_t bo = (wn * 16 + b_row) * 144 + b_kb;
        mlp_layer<4, 2>(sb + B_XB + ao, sb + B_XB + 9216 + ao,
                        sb + B_WB + 53248 + bo, sb + B_WB + 57856 + bo, 144, acc);
        epi_to_f32(acc, Bs + 128, H3, wm, wn, g, t);
    }
    __syncthreads();

    // ---- outputs ----
    for (int idx = tid; idx < TMROWS * 8; idx += NT) {
        int r = idx >> 3, f4 = idx & 7;
        float4 v = *(float4*)&H3[r * 36 + (f4 << 2)];
        *(float4*)&out_bonds[(size_t)(base + r) * 32 + (f4 << 2)] = v;
    }
    for (int r = wid; r < TMROWS; r += 8)
        atomicAdd(&g_b2a[(size_t)A1s[r] * 32 + lane], H3[r * 36 + lane]);
    if (tid < 32) {
        float ssum = 0.f;
        for (int r = 0; r < TMROWS; r++) ssum += H3[r * 36 + tid];
        atomicAdd(&g_bsum[tid], ssum);
    }
}

// ================= phi_v over atoms =================
__global__ void __launch_bounds__(NT, 2) atom_kernel(
    const float* __restrict__ atoms, const float* __restrict__ state,
    const float* __restrict__ vb1, const float* __restrict__ vb2,
    const float* __restrict__ vb3,
    float* __restrict__ out_atoms, int n_atoms)
{
    extern __shared__ char smem[];
    const uint32_t sb = smem_u32(smem);
    const int tid  = threadIdx.x;
    const int wid  = tid >> 5;
    const int lane = tid & 31;
    const int g = lane >> 2, t = lane & 3;
    const int wm = wid >> 1, wn = wid & 1;
    const int base = blockIdx.x * TMROWS;

    float* Bs = (float*)(smem + A_BIAS);
    uint32_t* Xh = (uint32_t*)(smem + A_XB);
    uint32_t* Xl = (uint32_t*)(smem + A_XB + 13312);
    uint32_t* Hh = (uint32_t*)(smem + A_XB);
    uint32_t* Hl = (uint32_t*)(smem + A_XB + 9216);
    float*    H3 = (float*)(smem + A_XB + 18432);

    {
        const int4* src = (const int4*)g_wv;
        int4* dst = (int4*)(smem + A_WB);
        for (int i = tid; i < 54272 / 16; i += NT) dst[i] = src[i];
    }
    if (tid < 64) { Bs[tid] = vb1[tid]; Bs[64 + tid] = vb2[tid]; }
    else if (tid < 96) Bs[128 + tid - 64] = vb3[tid - 64];

    // ---- stage X: 64 rows x 3 thirds of 32 elems (quarter 3 idle) ----
    {
        const int m = tid >> 2, q = tid & 3;
        if (q < 3) {
            const int gm = base + m;
            const int id = gm < n_atoms ? gm : n_atoms - 1;
            float f[32];
            if (q == 0) {
                float inv = 1.0f / g_cnt[id];
#pragma unroll
                for (int p = 0; p < 8; p++) {
                    float4 v = *(const float4*)&g_b2a[(size_t)id * 32 + 4 * p];
                    f[4 * p] = v.x * inv; f[4 * p + 1] = v.y * inv;
                    f[4 * p + 2] = v.z * inv; f[4 * p + 3] = v.w * inv;
                }
            } else {
                const float* src = (q == 1) ? atoms + (size_t)id * 32 : state;
#pragma unroll
                for (int p = 0; p < 8; p++) {
                    float4 v = *(const float4*)(src + 4 * p);
                    f[4 * p] = v.x; f[4 * p + 1] = v.y; f[4 * p + 2] = v.z; f[4 * p + 3] = v.w;
                }
            }
            const int wbase = m * 52 + q * 16;
#pragma unroll
            for (int p = 0; p < 16; p++) {
                uint32_t hw, lw;
                split_pair(f[2 * p], f[2 * p + 1], hw, lw);
                Xh[wbase + p] = hw;
                Xl[wbase + p] = lw;
            }
        }
    }
    __syncthreads();

    const uint32_t a_row = (uint32_t)(wm * 16 + (lane & 15));
    const uint32_t a_kb  = (uint32_t)((lane >> 4) << 4);
    const uint32_t b_row = (uint32_t)(((lane >> 4) << 3) + (lane & 7));
    const uint32_t b_kb  = (uint32_t)(((lane >> 3) & 1) << 4);

    // ---- layer 1: K=96 (A stride 208B), V1 stride 208B ----
    {
        float acc[4][4];
        uint32_t ao = a_row * 208 + a_kb;
        uint32_t bo = (wn * 32 + b_row) * 208 + b_kb;
        mlp_layer<6, 4>(sb + A_XB + ao, sb + A_XB + 13312 + ao,
                        sb + A_WB + bo, sb + A_WB + 13312 + bo, 208, acc);
        __syncthreads();
        epi_to_h<4>(acc, Bs, Hh, Hl, wm, wn, g, t);
    }
    __syncthreads();

    // ---- layer 2 ----
    {
        float acc[4][4];
        uint32_t ao = a_row * 144 + a_kb;
        uint32_t bo = (wn * 32 + b_row) * 144 + b_kb;
        mlp_layer<4, 4>(sb + A_XB + ao, sb + A_XB + 9216 + ao,
                        sb + A_WB + 26624 + bo, sb + A_WB + 35840 + bo, 144, acc);
        __syncthreads();
        epi_to_h<4>(acc, Bs + 64, Hh, Hl, wm, wn, g, t);
    }
    __syncthreads();

    // ---- layer 3 ----
    {
        float acc[2][4];
        uint32_t ao = a_row * 144 + a_kb;
        uint32_t bo = (wn * 16 + b_row) * 144 + b_kb;
        mlp_layer<4, 2>(sb + A_XB + ao, sb + A_XB + 9216 + ao,
                        sb + A_WB + 45056 + bo, sb + A_WB + 49664 + bo, 144, acc);
        epi_to_f32(acc, Bs + 128, H3, wm, wn, g, t);
    }
    __syncthreads();

    for (int idx = tid; idx < TMROWS * 8; idx += NT) {
        int r = idx >> 3, f4 = idx & 7;
        if (base + r < n_atoms) {
            float4 v = *(float4*)&H3[r * 36 + (f4 << 2)];
            *(float4*)&out_atoms[(size_t)(base + r) * 32 + (f4 << 2)] = v;
        }
    }
    if (tid < 32) {
        float ssum = 0.f;
        for (int r = 0; r < TMROWS; r++)
            if (base + r < n_atoms) ssum += H3[r * 36 + tid];
        atomicAdd(&g_asum[tid], ssum);
    }
}

// ================= phi_u =================
__global__ void state_kernel(
    const float* __restrict__ state,
    const float* __restrict__ uw1, const float* __restrict__ ub1,
    const float* __restrict__ uw2, const float* __restrict__ ub2,
    const float* __restrict__ uw3, const float* __restrict__ ub3,
    float* __restrict__ out_state, int n_bonds, int n_atoms)
{
    __shared__ float x[96], h1[64], h2[64];
    int tid = threadIdx.x;  // 64 threads
    if (tid < 32) {
        x[tid]      = g_bsum[tid] / (float)n_bonds;
        x[32 + tid] = g_asum[tid] / (float)n_atoms;
        x[64 + tid] = state[tid];
    }
    __syncthreads();
    {
        float a = ub1[tid];
        for (int k = 0; k < 96; k++) a = fmaf(x[k], uw1[k * 64 + tid], a);
        h1[tid] = selu_f(a);
    }
    __syncthreads();
    {
        float a = ub2[tid];
        for (int k = 0; k < 64; k++) a = fmaf(h1[k], uw2[k * 64 + tid], a);
        h2[tid] = selu_f(a);
    }
    __syncthreads();
    if (tid < 32) {
        float a = ub3[tid];
        for (int k = 0; k < 64; k++) a = fmaf(h2[k], uw3[k * 32 + tid], a);
        out_state[tid] = selu_f(a);
    }
}

// ================= launch =================
extern "C" void kernel_launch(void* const* d_in, const int* in_sizes, int n_in,
                              void* d_out, int out_size)
{
    const float* bonds = (const float*)d_in[0];
    const int*   ba1   = (const int*)d_in[1];
    const int*   ba2   = (const int*)d_in[2];
    const float* atoms = (const float*)d_in[3];
    const float* state = (const float*)d_in[4];
    const float* ew1 = (const float*)d_in[5];
    const float* eb1 = (const float*)d_in[6];
    const float* ew2 = (const float*)d_in[7];
    const float* eb2 = (const float*)d_in[8];
    const float* ew3 = (const float*)d_in[9];
    const float* eb3 = (const float*)d_in[10];
    const float* vw1 = (const float*)d_in[11];
    const float* vb1 = (const float*)d_in[12];
    const float* vw2 = (const float*)d_in[13];
    const float* vb2 = (const float*)d_in[14];
    const float* vw3 = (const float*)d_in[15];
    const float* vb3 = (const float*)d_in[16];
    const float* uw1 = (const float*)d_in[17];
    const float* ub1 = (const float*)d_in[18];
    const float* uw2 = (const float*)d_in[19];
    const float* ub2 = (const float*)d_in[20];
    const float* uw3 = (const float*)d_in[21];
    const float* ub3 = (const float*)d_in[22];

    const int n_bonds = in_sizes[1];
    const int n_atoms = in_sizes[3] / 32;

    float* out       = (float*)d_out;
    float* out_bonds = out;
    float* out_atoms = out + (size_t)n_bonds * 32;
    float* out_state = out_atoms + (size_t)n_atoms * 32;

    cudaFuncSetAttribute(bond_kernel, cudaFuncAttributeMaxDynamicSharedMemorySize, B_SMEM);
    cudaFuncSetAttribute(atom_kernel, cudaFuncAttributeMaxDynamicSharedMemorySize, A_SMEM);

    zero_kernel<<<256, 256>>>(n_atoms);
    prep_kernel<<<(29184 + 255) / 256, 256>>>(ew1, ew2, ew3, vw1, vw2, vw3);

    int bond_blocks = n_bonds / TMROWS;
    bond_kernel<<<bond_blocks, NT, B_SMEM>>>(
        bonds, ba1, ba2, atoms, state, eb1, eb2, eb3, out_bonds, n_bonds);

    int atom_blocks = (n_atoms + TMROWS - 1) / TMROWS;
    atom_kernel<<<atom_blocks, NT, A_SMEM>>>(
        atoms, state, vb1, vb2, vb3, out_atoms, n_atoms);

    state_kernel<<<1, 64>>>(state, uw1, ub1, uw2, ub2, uw3, ub3,
                            out_state, n_bonds, n_atoms);
}

// round 7
// speedup vs baseline: 4.9389x; 1.5261x over previous
#include <cuda_runtime.h>
#include <cuda_fp16.h>
#include <math.h>
#include <stdint.h>

// ================= scratch (no allocations allowed) =================
#define MAX_ATOMS 100000
__device__ float g_b2a[MAX_ATOMS * 32];
__device__ float g_cnt[MAX_ATOMS];
__device__ float g_bsum[32];
__device__ float g_asum[32];

// pre-transposed fp16 weight images Wt[n][k], padded k-stride (single stream)
// e: W1 64x136 @0, W2 64x72 @8704, W3 32x72 @13312  = 15616 halves
// v: V1 64x104 @0, V2 64x72 @6656, V3 32x72 @11264  = 13568 halves
__device__ __align__(16) __half g_we[15616];
__device__ __align__(16) __half g_wv[13568];

__device__ __forceinline__ float selu_f(float x) {
    const float lam = 1.0507009873554805f;
    const float la  = 1.7580993408473766f;
    float e = __expf(x);
    return x > 0.f ? lam * x : fmaf(la, e, -la);
}

// fp32 pair -> fp16x2 hi word + fp16x2 residual word (~22-bit combined)
__device__ __forceinline__ void split_pair(float v0, float v1, uint32_t& hw, uint32_t& lw) {
    __half h0 = __float2half(v0), h1 = __float2half(v1);
    __half2 hp; hp.x = h0; hp.y = h1;
    __half2 lp;
    lp.x = __float2half(v0 - __half2float(h0));
    lp.y = __float2half(v1 - __half2float(h1));
    hw = *(uint32_t*)&hp;
    lw = *(uint32_t*)&lp;
}

__device__ __forceinline__ uint32_t smem_u32(const void* p) {
    uint32_t a;
    asm("{ .reg .u64 t; cvta.to.shared.u64 t, %1; cvt.u32.u64 %0, t; }" : "=r"(a) : "l"(p));
    return a;
}

// ---- baseline-ISA tensor ops (valid on plain sm_100) ----
__device__ __forceinline__ void ldmx4(uint32_t r[4], uint32_t addr) {
    asm volatile("ldmatrix.sync.aligned.m8n8.x4.shared.b16 {%0,%1,%2,%3}, [%4];"
        : "=r"(r[0]), "=r"(r[1]), "=r"(r[2]), "=r"(r[3]) : "r"(addr));
}
__device__ __forceinline__ void mma_f16(float c[4], const uint32_t a[4], uint32_t b0, uint32_t b1) {
    asm("mma.sync.aligned.m16n8k16.row.col.f32.f16.f16.f32 "
        "{%0,%1,%2,%3}, {%4,%5,%6,%7}, {%8,%9}, {%0,%1,%2,%3};"
        : "+f"(c[0]), "+f"(c[1]), "+f"(c[2]), "+f"(c[3])
        : "r"(a[0]), "r"(a[1]), "r"(a[2]), "r"(a[3]), "r"(b0), "r"(b1));
}

// one dense layer: acc[NTW][4] += A(16 rows x K) @ Wt^T  (fp16 2-pass: xh*w + xl*w)
template <int KS, int NTW>
__device__ __forceinline__ void mlp_layer(
    uint32_t xh_addr, uint32_t xl_addr,
    uint32_t b_addr, uint32_t sbwB,
    float acc[NTW][4])
{
#pragma unroll
    for (int j = 0; j < NTW; j++)
#pragma unroll
        for (int q = 0; q < 4; q++) acc[j][q] = 0.f;

#pragma unroll
    for (int k = 0; k < KS; k++) {
        uint32_t ah[4], al[4];
        ldmx4(ah, xh_addr);
        ldmx4(al, xl_addr);
        xh_addr += 32; xl_addr += 32;
#pragma unroll
        for (int p = 0; p < NTW / 2; p++) {
            uint32_t rw[4];
            ldmx4(rw, b_addr + p * 8 * sbwB * 2);
            mma_f16(acc[2 * p],     ah, rw[0], rw[1]);
            mma_f16(acc[2 * p + 1], ah, rw[2], rw[3]);
            mma_f16(acc[2 * p],     al, rw[0], rw[1]);
            mma_f16(acc[2 * p + 1], al, rw[2], rw[3]);
        }
        b_addr += 32;
    }
}

// epilogue: bias+selu -> split -> fp16 H images (stride 36 words)
template <int NTW>
__device__ __forceinline__ void epi_to_h(
    float acc[NTW][4], const float* bias,
    uint32_t* Hh, uint32_t* Hl, int wm, int wn, int g, int t)
{
    const int r0 = wm * 16 + g;
#pragma unroll
    for (int j = 0; j < NTW; j++) {
        int col = wn * 32 + j * 8 + 2 * t;
        int cw  = wn * 16 + j * 4 + t;
        float b0 = bias[col], b1 = bias[col + 1];
        uint32_t hw, lw;
        split_pair(selu_f(acc[j][0] + b0), selu_f(acc[j][1] + b1), hw, lw);
        Hh[r0 * 36 + cw] = hw; Hl[r0 * 36 + cw] = lw;
        split_pair(selu_f(acc[j][2] + b0), selu_f(acc[j][3] + b1), hw, lw);
        Hh[(r0 + 8) * 36 + cw] = hw; Hl[(r0 + 8) * 36 + cw] = lw;
    }
}

// epilogue: bias+selu -> fp32 H3 staging [rows][36]  (N=32, NTW=2)
__device__ __forceinline__ void epi_to_f32(
    float acc[2][4], const float* bias, float* H3, int wm, int wn, int g, int t)
{
    const int r0 = wm * 16 + g;
#pragma unroll
    for (int j = 0; j < 2; j++) {
        int col = wn * 16 + j * 8 + 2 * t;
        float b0 = bias[col], b1 = bias[col + 1];
        float2 v;
        v.x = selu_f(acc[j][0] + b0);
        v.y = selu_f(acc[j][1] + b1);
        *(float2*)&H3[r0 * 36 + col] = v;
        v.x = selu_f(acc[j][2] + b0);
        v.y = selu_f(acc[j][3] + b1);
        *(float2*)&H3[(r0 + 8) * 36 + col] = v;
    }
}

// ================= zero scratch =================
__global__ void zero_kernel(int n_atoms)
{
    int i = blockIdx.x * blockDim.x + threadIdx.x;
    int stride = gridDim.x * blockDim.x;
    int nb = n_atoms * 32;
    for (int idx = i; idx < nb; idx += stride) g_b2a[idx] = 0.f;
    for (int idx = i; idx < n_atoms; idx += stride) g_cnt[idx] = 0.f;
    if (i < 32) { g_bsum[i] = 0.f; g_asum[i] = 0.f; }
}

// ================= weight transpose prep (fp16 single stream) =================
__global__ void prep_kernel(
    const float* __restrict__ ew1, const float* __restrict__ ew2, const float* __restrict__ ew3,
    const float* __restrict__ vw1, const float* __restrict__ vw2, const float* __restrict__ vw3)
{
    int i = blockIdx.x * blockDim.x + threadIdx.x;
    if (i >= 29184) return;
    const float* src; __half* img;
    int stride, N, Ksrc, local;
    if (i < 8704)        { local = i;         stride = 136; N = 64; Ksrc = 128; src = ew1; img = g_we; }
    else if (i < 13312)  { local = i - 8704;  stride = 72;  N = 64; Ksrc = 64;  src = ew2; img = g_we + 8704; }
    else if (i < 15616)  { local = i - 13312; stride = 72;  N = 32; Ksrc = 64;  src = ew3; img = g_we + 13312; }
    else if (i < 22272)  { local = i - 15616; stride = 104; N = 64; Ksrc = 96;  src = vw1; img = g_wv; }
    else if (i < 26880)  { local = i - 22272; stride = 72;  N = 64; Ksrc = 64;  src = vw2; img = g_wv + 6656; }
    else                 { local = i - 26880; stride = 72;  N = 32; Ksrc = 64;  src = vw3; img = g_wv + 11264; }
    int n = local / stride, k = local % stride;
    float w = (k < Ksrc) ? src[k * N + n] : 0.f;
    img[local] = __float2half(w);
}

// ================= smem maps (bytes) =================
// bond: X region 34816 (Xh 17408 + Xl 17408); H overlay 9216+9216; H3 @+18432
#define B_BIAS   0
#define B_A1S    640
#define B_XB     1024
#define B_WB     35840    // W1 @+0, W2 @+17408, W3 @+26624 (bytes)
#define B_SMEM   67072
// atom: X region 27648 (Xh 13312 + Xl 13312, H3 @+18432)
#define A_BIAS   0
#define A_XB     768
#define A_WB     28416    // V1 @+0, V2 @+13312, V3 @+22528
#define A_SMEM   55552

#define NT 256
#define TMROWS 64

// ================= phi_e over bonds =================
__global__ void __launch_bounds__(NT, 3) bond_kernel(
    const float* __restrict__ bonds, const int* __restrict__ ba1,
    const int* __restrict__ ba2, const float* __restrict__ atoms,
    const float* __restrict__ state,
    const float* __restrict__ eb1, const float* __restrict__ eb2,
    const float* __restrict__ eb3,
    float* __restrict__ out_bonds, int n_bonds)
{
    extern __shared__ char smem[];
    const uint32_t sb = smem_u32(smem);
    const int tid  = threadIdx.x;
    const int wid  = tid >> 5;
    const int lane = tid & 31;
    const int g = lane >> 2, t = lane & 3;
    const int wm = wid >> 1, wn = wid & 1;   // 4 m-tiles x 2 n-tiles
    const int base = blockIdx.x * TMROWS;

    float* Bs  = (float*)(smem + B_BIAS);
    int*   A1s = (int*)(smem + B_A1S);
    uint32_t* Xh = (uint32_t*)(smem + B_XB);
    uint32_t* Xl = (uint32_t*)(smem + B_XB + 17408);
    uint32_t* Hh = (uint32_t*)(smem + B_XB);
    uint32_t* Hl = (uint32_t*)(smem + B_XB + 9216);
    float*    H3 = (float*)(smem + B_XB + 18432);

    // weights -> smem (bulk copy, L2-hot)
    {
        const int4* src = (const int4*)g_we;
        int4* dst = (int4*)(smem + B_WB);
        for (int i = tid; i < 31232 / 16; i += NT) dst[i] = src[i];
    }
    if (tid < 64) { Bs[tid] = eb1[tid]; Bs[64 + tid] = eb2[tid]; }
    else if (tid < 96) Bs[128 + tid - 64] = eb3[tid - 64];

    // ---- stage X: 64 rows x 4 quarters of 32 elems (stream, low reg pressure) ----
    {
        const int m = tid >> 2, q = tid & 3;
        const int gid = base + m;
        const float* src;
        if (q == 0) {
            int a1 = ba1[gid];
            A1s[m] = a1;
            atomicAdd(&g_cnt[a1], 1.0f);
            src = atoms + (size_t)a1 * 32;
        } else if (q == 1) {
            src = atoms + (size_t)ba2[gid] * 32;
        } else if (q == 2) {
            src = bonds + (size_t)gid * 32;
        } else {
            src = state;
        }
        const int wbase = m * 68 + q * 16;
#pragma unroll
        for (int p = 0; p < 8; p++) {
            float4 v = *(const float4*)(src + 4 * p);
            uint32_t hw, lw;
            split_pair(v.x, v.y, hw, lw);
            Xh[wbase + 2 * p] = hw; Xl[wbase + 2 * p] = lw;
            split_pair(v.z, v.w, hw, lw);
            Xh[wbase + 2 * p + 1] = hw; Xl[wbase + 2 * p + 1] = lw;
        }
    }
    __syncthreads();

    // lane-resolved fragment addresses
    const uint32_t a_row = (uint32_t)(wm * 16 + (lane & 15));
    const uint32_t a_kb  = (uint32_t)((lane >> 4) << 4);
    const uint32_t b_row = (uint32_t)(((lane >> 4) << 3) + (lane & 7));
    const uint32_t b_kb  = (uint32_t)(((lane >> 3) & 1) << 4);

    // ---- layer 1: K=128 (A stride 272B), W1 stride 272B, N=64 ----
    {
        float acc[4][4];
        uint32_t ao = a_row * 272 + a_kb;
        uint32_t bo = (wn * 32 + b_row) * 272 + b_kb;
        mlp_layer<8, 4>(sb + B_XB + ao, sb + B_XB + 17408 + ao,
                        sb + B_WB + bo, 272, acc);
        __syncthreads();  // all reads of X done before H overwrites it
        epi_to_h<4>(acc, Bs, Hh, Hl, wm, wn, g, t);
    }
    __syncthreads();

    // ---- layer 2: K=64 (A stride 144B), W2 stride 144B, N=64 ----
    {
        float acc[4][4];
        uint32_t ao = a_row * 144 + a_kb;
        uint32_t bo = (wn * 32 + b_row) * 144 + b_kb;
        mlp_layer<4, 4>(sb + B_XB + ao, sb + B_XB + 9216 + ao,
                        sb + B_WB + 17408 + bo, 144, acc);
        __syncthreads();
        epi_to_h<4>(acc, Bs + 64, Hh, Hl, wm, wn, g, t);
    }
    __syncthreads();

    // ---- layer 3: K=64, N=32, W3 stride 144B ----
    {
        float acc[2][4];
        uint32_t ao = a_row * 144 + a_kb;
        uint32_t bo = (wn * 16 + b_row) * 144 + b_kb;
        mlp_layer<4, 2>(sb + B_XB + ao, sb + B_XB + 9216 + ao,
                        sb + B_WB + 26624 + bo, 144, acc);
        epi_to_f32(acc, Bs + 128, H3, wm, wn, g, t);
    }
    __syncthreads();

    // ---- outputs ----
    for (int idx = tid; idx < TMROWS * 8; idx += NT) {
        int r = idx >> 3, f4 = idx & 7;
        float4 v = *(float4*)&H3[r * 36 + (f4 << 2)];
        *(float4*)&out_bonds[(size_t)(base + r) * 32 + (f4 << 2)] = v;
    }
    for (int r = wid; r < TMROWS; r += 8)
        atomicAdd(&g_b2a[(size_t)A1s[r] * 32 + lane], H3[r * 36 + lane]);
    if (tid < 32) {
        float ssum = 0.f;
        for (int r = 0; r < TMROWS; r++) ssum += H3[r * 36 + tid];
        atomicAdd(&g_bsum[tid], ssum);
    }
}

// ================= phi_v over atoms =================
__global__ void __launch_bounds__(NT, 3) atom_kernel(
    const float* __restrict__ atoms, const float* __restrict__ state,
    const float* __restrict__ vb1, const float* __restrict__ vb2,
    const float* __restrict__ vb3,
    float* __restrict__ out_atoms, int n_atoms)
{
    extern __shared__ char smem[];
    const uint32_t sb = smem_u32(smem);
    const int tid  = threadIdx.x;
    const int wid  = tid >> 5;
    const int lane = tid & 31;
    const int g = lane >> 2, t = lane & 3;
    const int wm = wid >> 1, wn = wid & 1;
    const int base = blockIdx.x * TMROWS;

    float* Bs = (float*)(smem + A_BIAS);
    uint32_t* Xh = (uint32_t*)(smem + A_XB);
    uint32_t* Xl = (uint32_t*)(smem + A_XB + 13312);
    uint32_t* Hh = (uint32_t*)(smem + A_XB);
    uint32_t* Hl = (uint32_t*)(smem + A_XB + 9216);
    float*    H3 = (float*)(smem + A_XB + 18432);

    {
        const int4* src = (const int4*)g_wv;
        int4* dst = (int4*)(smem + A_WB);
        for (int i = tid; i < 27136 / 16; i += NT) dst[i] = src[i];
    }
    if (tid < 64) { Bs[tid] = vb1[tid]; Bs[64 + tid] = vb2[tid]; }
    else if (tid < 96) Bs[128 + tid - 64] = vb3[tid - 64];

    // ---- stage X: 64 rows x 3 thirds of 32 elems (quarter 3 idle) ----
    {
        const int m = tid >> 2, q = tid & 3;
        if (q < 3) {
            const int gm = base + m;
            const int id = gm < n_atoms ? gm : n_atoms - 1;
            const int wbase = m * 52 + q * 16;
            if (q == 0) {
                float inv = 1.0f / g_cnt[id];
#pragma unroll
                for (int p = 0; p < 8; p++) {
                    float4 v = *(const float4*)&g_b2a[(size_t)id * 32 + 4 * p];
                    uint32_t hw, lw;
                    split_pair(v.x * inv, v.y * inv, hw, lw);
                    Xh[wbase + 2 * p] = hw; Xl[wbase + 2 * p] = lw;
                    split_pair(v.z * inv, v.w * inv, hw, lw);
                    Xh[wbase + 2 * p + 1] = hw; Xl[wbase + 2 * p + 1] = lw;
                }
            } else {
                const float* src = (q == 1) ? atoms + (size_t)id * 32 : state;
#pragma unroll
                for (int p = 0; p < 8; p++) {
                    float4 v = *(const float4*)(src + 4 * p);
                    uint32_t hw, lw;
                    split_pair(v.x, v.y, hw, lw);
                    Xh[wbase + 2 * p] = hw; Xl[wbase + 2 * p] = lw;
                    split_pair(v.z, v.w, hw, lw);
                    Xh[wbase + 2 * p + 1] = hw; Xl[wbase + 2 * p + 1] = lw;
                }
            }
        }
    }
    __syncthreads();

    const uint32_t a_row = (uint32_t)(wm * 16 + (lane & 15));
    const uint32_t a_kb  = (uint32_t)((lane >> 4) << 4);
    const uint32_t b_row = (uint32_t)(((lane >> 4) << 3) + (lane & 7));
    const uint32_t b_kb  = (uint32_t)(((lane >> 3) & 1) << 4);

    // ---- layer 1: K=96 (A stride 208B), V1 stride 208B ----
    {
        float acc[4][4];
        uint32_t ao = a_row * 208 + a_kb;
        uint32_t bo = (wn * 32 + b_row) * 208 + b_kb;
        mlp_layer<6, 4>(sb + A_XB + ao, sb + A_XB + 13312 + ao,
                        sb + A_WB + bo, 208, acc);
        __syncthreads();
        epi_to_h<4>(acc, Bs, Hh, Hl, wm, wn, g, t);
    }
    __syncthreads();

    // ---- layer 2 ----
    {
        float acc[4][4];
        uint32_t ao = a_row * 144 + a_kb;
        uint32_t bo = (wn * 32 + b_row) * 144 + b_kb;
        mlp_layer<4, 4>(sb + A_XB + ao, sb + A_XB + 9216 + ao,
                        sb + A_WB + 13312 + bo, 144, acc);
        __syncthreads();
        epi_to_h<4>(acc, Bs + 64, Hh, Hl, wm, wn, g, t);
    }
    __syncthreads();

    // ---- layer 3 ----
    {
        float acc[2][4];
        uint32_t ao = a_row * 144 + a_kb;
        uint32_t bo = (wn * 16 + b_row) * 144 + b_kb;
        mlp_layer<4, 2>(sb + A_XB + ao, sb + A_XB + 9216 + ao,
                        sb + A_WB + 22528 + bo, 144, acc);
        epi_to_f32(acc, Bs + 128, H3, wm, wn, g, t);
    }
    __syncthreads();

    for (int idx = tid; idx < TMROWS * 8; idx += NT) {
        int r = idx >> 3, f4 = idx & 7;
        if (base + r < n_atoms) {
            float4 v = *(float4*)&H3[r * 36 + (f4 << 2)];
            *(float4*)&out_atoms[(size_t)(base + r) * 32 + (f4 << 2)] = v;
        }
    }
    if (tid < 32) {
        float ssum = 0.f;
        for (int r = 0; r < TMROWS; r++)
            if (base + r < n_atoms) ssum += H3[r * 36 + tid];
        atomicAdd(&g_asum[tid], ssum);
    }
}

// ================= phi_u =================
__global__ void state_kernel(
    const float* __restrict__ state,
    const float* __restrict__ uw1, const float* __restrict__ ub1,
    const float* __restrict__ uw2, const float* __restrict__ ub2,
    const float* __restrict__ uw3, const float* __restrict__ ub3,
    float* __restrict__ out_state, int n_bonds, int n_atoms)
{
    __shared__ float x[96], h1[64], h2[64];
    int tid = threadIdx.x;  // 64 threads
    if (tid < 32) {
        x[tid]      = g_bsum[tid] / (float)n_bonds;
        x[32 + tid] = g_asum[tid] / (float)n_atoms;
        x[64 + tid] = state[tid];
    }
    __syncthreads();
    {
        float a = ub1[tid];
        for (int k = 0; k < 96; k++) a = fmaf(x[k], uw1[k * 64 + tid], a);
        h1[tid] = selu_f(a);
    }
    __syncthreads();
    {
        float a = ub2[tid];
        for (int k = 0; k < 64; k++) a = fmaf(h1[k], uw2[k * 64 + tid], a);
        h2[tid] = selu_f(a);
    }
    __syncthreads();
    if (tid < 32) {
        float a = ub3[tid];
        for (int k = 0; k < 64; k++) a = fmaf(h2[k], uw3[k * 32 + tid], a);
        out_state[tid] = selu_f(a);
    }
}

// ================= launch =================
extern "C" void kernel_launch(void* const* d_in, const int* in_sizes, int n_in,
                              void* d_out, int out_size)
{
    const float* bonds = (const float*)d_in[0];
    const int*   ba1   = (const int*)d_in[1];
    const int*   ba2   = (const int*)d_in[2];
    const float* atoms = (const float*)d_in[3];
    const float* state = (const float*)d_in[4];
    const float* ew1 = (const float*)d_in[5];
    const float* eb1 = (const float*)d_in[6];
    const float* ew2 = (const float*)d_in[7];
    const float* eb2 = (const float*)d_in[8];
    const float* ew3 = (const float*)d_in[9];
    const float* eb3 = (const float*)d_in[10];
    const float* vw1 = (const float*)d_in[11];
    const float* vb1 = (const float*)d_in[12];
    const float* vw2 = (const float*)d_in[13];
    const float* vb2 = (const float*)d_in[14];
    const float* vw3 = (const float*)d_in[15];
    const float* vb3 = (const float*)d_in[16];
    const float* uw1 = (const float*)d_in[17];
    const float* ub1 = (const float*)d_in[18];
    const float* uw2 = (const float*)d_in[19];
    const float* ub2 = (const float*)d_in[20];
    const float* uw3 = (const float*)d_in[21];
    const float* ub3 = (const float*)d_in[22];

    const int n_bonds = in_sizes[1];
    const int n_atoms = in_sizes[3] / 32;

    float* out       = (float*)d_out;
    float* out_bonds = out;
    float* out_atoms = out + (size_t)n_bonds * 32;
    float* out_state = out_atoms + (size_t)n_atoms * 32;

    cudaFuncSetAttribute(bond_kernel, cudaFuncAttributeMaxDynamicSharedMemorySize, B_SMEM);
    cudaFuncSetAttribute(atom_kernel, cudaFuncAttributeMaxDynamicSharedMemorySize, A_SMEM);

    zero_kernel<<<256, 256>>>(n_atoms);
    prep_kernel<<<(29184 + 255) / 256, 256>>>(ew1, ew2, ew3, vw1, vw2, vw3);

    int bond_blocks = n_bonds / TMROWS;
    bond_kernel<<<bond_blocks, NT, B_SMEM>>>(
        bonds, ba1, ba2, atoms, state, eb1, eb2, eb3, out_bonds, n_bonds);

    int atom_blocks = (n_atoms + TMROWS - 1) / TMROWS;
    atom_kernel<<<atom_blocks, NT, A_SMEM>>>(
        atoms, state, vb1, vb2, vb3, out_atoms, n_atoms);

    state_kernel<<<1, 64>>>(state, uw1, ub1, uw2, ub2, uw3, ub3,
                            out_state, n_bonds, n_atoms);
}

// round 8
// speedup vs baseline: 4.9581x; 1.0039x over previous
#include <cuda_runtime.h>
#include <cuda_fp16.h>
#include <math.h>
#include <stdint.h>

// ================= scratch (no allocations allowed) =================
#define MAX_ATOMS 100000
__device__ float g_b2a[MAX_ATOMS * 32];
__device__ float g_cnt[MAX_ATOMS];
__device__ float g_bsum[32];
__device__ float g_asum[32];

// pre-transposed fp16 weight images Wt[n][k], padded k-stride (single stream)
__device__ __align__(16) __half g_we[15616];  // W1@0 W2@8704 W3@13312 (halves)
__device__ __align__(16) __half g_wv[13568];  // V1@0 V2@6656 V3@11264

__device__ __forceinline__ float selu_f(float x) {
    const float lam = 1.0507009873554805f;
    const float la  = 1.7580993408473766f;
    float e = __expf(x);
    return x > 0.f ? lam * x : fmaf(la, e, -la);
}

// fp32 pair -> fp16x2 hi word + fp16x2 residual word (packed cvt, ~22-bit combined)
__device__ __forceinline__ void split_pair(float v0, float v1, uint32_t& hw, uint32_t& lw) {
    __half2 hp = __floats2half2_rn(v0, v1);
    float2 hf = __half22float2(hp);
    __half2 lp = __floats2half2_rn(v0 - hf.x, v1 - hf.y);
    hw = *(uint32_t*)&hp;
    lw = *(uint32_t*)&lp;
}

__device__ __forceinline__ uint32_t smem_u32(const void* p) {
    uint32_t a;
    asm("{ .reg .u64 t; cvta.to.shared.u64 t, %1; cvt.u32.u64 %0, t; }" : "=r"(a) : "l"(p));
    return a;
}

// ---- baseline-ISA ops (valid on plain sm_100) ----
__device__ __forceinline__ void ldmx4(uint32_t r[4], uint32_t addr) {
    asm volatile("ldmatrix.sync.aligned.m8n8.x4.shared.b16 {%0,%1,%2,%3}, [%4];"
        : "=r"(r[0]), "=r"(r[1]), "=r"(r[2]), "=r"(r[3]) : "r"(addr));
}
__device__ __forceinline__ void mma_f16(float c[4], const uint32_t a[4], uint32_t b0, uint32_t b1) {
    asm("mma.sync.aligned.m16n8k16.row.col.f32.f16.f16.f32 "
        "{%0,%1,%2,%3}, {%4,%5,%6,%7}, {%8,%9}, {%0,%1,%2,%3};"
        : "+f"(c[0]), "+f"(c[1]), "+f"(c[2]), "+f"(c[3])
        : "r"(a[0]), "r"(a[1]), "r"(a[2]), "r"(a[3]), "r"(b0), "r"(b1));
}
__device__ __forceinline__ void cp16(uint32_t dst, const void* src) {
    asm volatile("cp.async.ca.shared.global [%0], [%1], 16;" :: "r"(dst), "l"(src));
}
#define CP_COMMIT() asm volatile("cp.async.commit_group;" ::: "memory")
#define CP_WAIT0()  asm volatile("cp.async.wait_group 0;" ::: "memory")

// dense layer, rm=2: acc[2][NTW][4] += A(2x16 rows x K) @ Wt^T  (fp16 2-pass)
template <int KS, int NTW>
__device__ __forceinline__ void mlp_layer2(
    uint32_t xh, uint32_t xl, uint32_t sA,
    uint32_t b_addr, uint32_t sB,
    float acc[2][NTW][4])
{
#pragma unroll
    for (int i = 0; i < 2; i++)
#pragma unroll
        for (int j = 0; j < NTW; j++)
#pragma unroll
            for (int q = 0; q < 4; q++) acc[i][j][q] = 0.f;

#pragma unroll
    for (int k = 0; k < KS; k++) {
        uint32_t ah[2][4], al[2][4];
#pragma unroll
        for (int i = 0; i < 2; i++) {
            ldmx4(ah[i], xh + i * 16 * sA);
            ldmx4(al[i], xl + i * 16 * sA);
        }
        xh += 32; xl += 32;
#pragma unroll
        for (int p = 0; p < NTW / 2; p++) {
            uint32_t rw[4];
            ldmx4(rw, b_addr + p * 16 * sB);
#pragma unroll
            for (int i = 0; i < 2; i++) {
                mma_f16(acc[i][2 * p],     ah[i], rw[0], rw[1]);
                mma_f16(acc[i][2 * p + 1], ah[i], rw[2], rw[3]);
                mma_f16(acc[i][2 * p],     al[i], rw[0], rw[1]);
                mma_f16(acc[i][2 * p + 1], al[i], rw[2], rw[3]);
            }
        }
        b_addr += 32;
    }
}

// epilogue: bias+selu -> split -> fp16 H images (stride 36 words)
template <int NTW>
__device__ __forceinline__ void epi_to_h2(
    float acc[2][NTW][4], const float* bias,
    uint32_t* Hh, uint32_t* Hl, int wm, int wn, int g, int t)
{
#pragma unroll
    for (int i = 0; i < 2; i++) {
        const int r0 = wm * 32 + i * 16 + g;
#pragma unroll
        for (int j = 0; j < NTW; j++) {
            int col = wn * 32 + j * 8 + 2 * t;
            int cw  = wn * 16 + j * 4 + t;
            float b0 = bias[col], b1 = bias[col + 1];
            uint32_t hw, lw;
            split_pair(selu_f(acc[i][j][0] + b0), selu_f(acc[i][j][1] + b1), hw, lw);
            Hh[r0 * 36 + cw] = hw; Hl[r0 * 36 + cw] = lw;
            split_pair(selu_f(acc[i][j][2] + b0), selu_f(acc[i][j][3] + b1), hw, lw);
            Hh[(r0 + 8) * 36 + cw] = hw; Hl[(r0 + 8) * 36 + cw] = lw;
        }
    }
}

// epilogue: bias+selu -> fp32 H3 [rows][36]  (N=32, NTW=2)
__device__ __forceinline__ void epi_to_f32_2(
    float acc[2][2][4], const float* bias, float* H3, int wm, int wn, int g, int t)
{
#pragma unroll
    for (int i = 0; i < 2; i++) {
        const int r0 = wm * 32 + i * 16 + g;
#pragma unroll
        for (int j = 0; j < 2; j++) {
            int col = wn * 16 + j * 8 + 2 * t;
            float b0 = bias[col], b1 = bias[col + 1];
            float2 v;
            v.x = selu_f(acc[i][j][0] + b0);
            v.y = selu_f(acc[i][j][1] + b1);
            *(float2*)&H3[r0 * 36 + col] = v;
            v.x = selu_f(acc[i][j][2] + b0);
            v.y = selu_f(acc[i][j][3] + b1);
            *(float2*)&H3[(r0 + 8) * 36 + col] = v;
        }
    }
}

// ================= zero scratch =================
__global__ void zero_kernel(int n_atoms)
{
    int i = blockIdx.x * blockDim.x + threadIdx.x;
    int stride = gridDim.x * blockDim.x;
    int nb = n_atoms * 32;
    for (int idx = i; idx < nb; idx += stride) g_b2a[idx] = 0.f;
    for (int idx = i; idx < n_atoms; idx += stride) g_cnt[idx] = 0.f;
    if (i < 32) { g_bsum[i] = 0.f; g_asum[i] = 0.f; }
}

// ================= weight transpose prep (fp16 single stream) =================
__global__ void prep_kernel(
    const float* __restrict__ ew1, const float* __restrict__ ew2, const float* __restrict__ ew3,
    const float* __restrict__ vw1, const float* __restrict__ vw2, const float* __restrict__ vw3)
{
    int i = blockIdx.x * blockDim.x + threadIdx.x;
    if (i >= 29184) return;
    const float* src; __half* img;
    int stride, N, Ksrc, local;
    if (i < 8704)        { local = i;         stride = 136; N = 64; Ksrc = 128; src = ew1; img = g_we; }
    else if (i < 13312)  { local = i - 8704;  stride = 72;  N = 64; Ksrc = 64;  src = ew2; img = g_we + 8704; }
    else if (i < 15616)  { local = i - 13312; stride = 72;  N = 32; Ksrc = 64;  src = ew3; img = g_we + 13312; }
    else if (i < 22272)  { local = i - 15616; stride = 104; N = 64; Ksrc = 96;  src = vw1; img = g_wv; }
    else if (i < 26880)  { local = i - 22272; stride = 72;  N = 64; Ksrc = 64;  src = vw2; img = g_wv + 6656; }
    else                 { local = i - 26880; stride = 72;  N = 32; Ksrc = 64;  src = vw3; img = g_wv + 11264; }
    int n = local / stride, k = local % stride;
    float w = (k < Ksrc) ? src[k * N + n] : 0.f;
    img[local] = __float2half(w);
}

// ================= smem maps (bytes) =================
// bond (128 rows): Xh 34816 + Xl 34816 = 69632; H overlay 18432+18432; H3 @+36864
#define B_BIAS   0
#define B_A1S    640
#define B_XB     1280
#define B_WB     70912    // W1 @+0, W2 @+17408, W3 @+26624 (bytes)
#define B_SMEM   102144
// atom (128 rows): Xh 26624 + Xl 26624 = 53248; region 55296 for H3 @+36864
#define A_BIAS   0
#define A_XB     768
#define A_WB     56064    // V1 @+0, V2 @+13312, V3 @+22528
#define A_SMEM   83200

#define NT 256
#define TMROWS 128

// ================= phi_e over bonds =================
__global__ void __launch_bounds__(NT, 2) bond_kernel(
    const float* __restrict__ bonds, const int* __restrict__ ba1,
    const int* __restrict__ ba2, const float* __restrict__ atoms,
    const float* __restrict__ state,
    const float* __restrict__ eb1, const float* __restrict__ eb2,
    const float* __restrict__ eb3,
    float* __restrict__ out_bonds, int n_bonds)
{
    extern __shared__ char smem[];
    const uint32_t sb = smem_u32(smem);
    const int tid  = threadIdx.x;
    const int wid  = tid >> 5;
    const int lane = tid & 31;
    const int g = lane >> 2, t = lane & 3;
    const int wm = wid >> 1, wn = wid & 1;   // 4 m-tiles (32 rows) x 2 n-tiles (32 cols)
    const int base = blockIdx.x * TMROWS;

    float* Bs  = (float*)(smem + B_BIAS);
    int*   A1s = (int*)(smem + B_A1S);
    uint32_t* Xh = (uint32_t*)(smem + B_XB);
    uint32_t* Xl = (uint32_t*)(smem + B_XB + 34816);
    uint32_t* Hh = (uint32_t*)(smem + B_XB);
    uint32_t* Hl = (uint32_t*)(smem + B_XB + 18432);
    float*    H3 = (float*)(smem + B_XB + 36864);

    // weights -> smem (cp.async, overlapped with staging)
    for (int i = tid; i < 31232 / 16; i += NT)
        cp16(sb + B_WB + i * 16, (const char*)g_we + i * 16);
    CP_COMMIT();
    if (tid < 64) { Bs[tid] = eb1[tid]; Bs[64 + tid] = eb2[tid]; }
    else if (tid < 96) Bs[128 + tid - 64] = eb3[tid - 64];

    // ---- stage X: 128 rows x 4 quarters of 32 elems ----
    for (int task = tid; task < TMROWS * 4; task += NT) {
        const int m = task >> 2, q = task & 3;
        const int gid = base + m;
        const float* src;
        if (q == 0) {
            int a1 = ba1[gid];
            A1s[m] = a1;
            atomicAdd(&g_cnt[a1], 1.0f);
            src = atoms + (size_t)a1 * 32;
        } else if (q == 1) {
            src = atoms + (size_t)ba2[gid] * 32;
        } else if (q == 2) {
            src = bonds + (size_t)gid * 32;
        } else {
            src = state;
        }
        const int wbase = m * 68 + q * 16;
#pragma unroll
        for (int p = 0; p < 8; p++) {
            float4 v = *(const float4*)(src + 4 * p);
            uint32_t hw, lw;
            split_pair(v.x, v.y, hw, lw);
            Xh[wbase + 2 * p] = hw; Xl[wbase + 2 * p] = lw;
            split_pair(v.z, v.w, hw, lw);
            Xh[wbase + 2 * p + 1] = hw; Xl[wbase + 2 * p + 1] = lw;
        }
    }
    CP_WAIT0();
    __syncthreads();

    // lane-resolved fragment addresses
    const uint32_t a_row = (uint32_t)(wm * 32 + (lane & 15));
    const uint32_t a_kb  = (uint32_t)((lane >> 4) << 4);
    const uint32_t b_row = (uint32_t)(((lane >> 4) << 3) + (lane & 7));
    const uint32_t b_kb  = (uint32_t)(((lane >> 3) & 1) << 4);

    // ---- layer 1: K=128 (strides 272B) ----
    {
        float acc[2][4][4];
        uint32_t ao = a_row * 272 + a_kb;
        uint32_t bo = (wn * 32 + b_row) * 272 + b_kb;
        mlp_layer2<8, 4>(sb + B_XB + ao, sb + B_XB + 34816 + ao, 272,
                         sb + B_WB + bo, 272, acc);
        __syncthreads();  // X reads done before H overwrites
        epi_to_h2<4>(acc, Bs, Hh, Hl, wm, wn, g, t);
    }
    __syncthreads();

    // ---- layer 2: K=64 (strides 144B) ----
    {
        float acc[2][4][4];
        uint32_t ao = a_row * 144 + a_kb;
        uint32_t bo = (wn * 32 + b_row) * 144 + b_kb;
        mlp_layer2<4, 4>(sb + B_XB + ao, sb + B_XB + 18432 + ao, 144,
                         sb + B_WB + 17408 + bo, 144, acc);
        __syncthreads();
        epi_to_h2<4>(acc, Bs + 64, Hh, Hl, wm, wn, g, t);
    }
    __syncthreads();

    // ---- layer 3: K=64, N=32 ----
    {
        float acc[2][2][4];
        uint32_t ao = a_row * 144 + a_kb;
        uint32_t bo = (wn * 16 + b_row) * 144 + b_kb;
        mlp_layer2<4, 2>(sb + B_XB + ao, sb + B_XB + 18432 + ao, 144,
                         sb + B_WB + 26624 + bo, 144, acc);
        epi_to_f32_2(acc, Bs + 128, H3, wm, wn, g, t);
    }
    __syncthreads();

    // ---- outputs ----
    for (int idx = tid; idx < TMROWS * 8; idx += NT) {
        int r = idx >> 3, f4 = idx & 7;
        float4 v = *(float4*)&H3[r * 36 + (f4 << 2)];
        *(float4*)&out_bonds[(size_t)(base + r) * 32 + (f4 << 2)] = v;
    }
    for (int r = wid; r < TMROWS; r += 8)
        atomicAdd(&g_b2a[(size_t)A1s[r] * 32 + lane], H3[r * 36 + lane]);
    if (tid < 32) {
        float ssum = 0.f;
        for (int r = 0; r < TMROWS; r++) ssum += H3[r * 36 + tid];
        atomicAdd(&g_bsum[tid], ssum);
    }
}

// ================= phi_v over atoms =================
__global__ void __launch_bounds__(NT, 2) atom_kernel(
    const float* __restrict__ atoms, const float* __restrict__ state,
    const float* __restrict__ vb1, const float* __restrict__ vb2,
    const float* __restrict__ vb3,
    float* __restrict__ out_atoms, int n_atoms)
{
    extern __shared__ char smem[];
    const uint32_t sb = smem_u32(smem);
    const int tid  = threadIdx.x;
    const int wid  = tid >> 5;
    const int lane = tid & 31;
    const int g = lane >> 2, t = lane & 3;
    const int wm = wid >> 1, wn = wid & 1;
    const int base = blockIdx.x * TMROWS;

    float* Bs = (float*)(smem + A_BIAS);
    uint32_t* Xh = (uint32_t*)(smem + A_XB);
    uint32_t* Xl = (uint32_t*)(smem + A_XB + 26624);
    uint32_t* Hh = (uint32_t*)(smem + A_XB);
    uint32_t* Hl = (uint32_t*)(smem + A_XB + 18432);
    float*    H3 = (float*)(smem + A_XB + 36864);

    for (int i = tid; i < 27136 / 16; i += NT)
        cp16(sb + A_WB + i * 16, (const char*)g_wv + i * 16);
    CP_COMMIT();
    if (tid < 64) { Bs[tid] = vb1[tid]; Bs[64 + tid] = vb2[tid]; }
    else if (tid < 96) Bs[128 + tid - 64] = vb3[tid - 64];

    // ---- stage X: 128 rows x 3 thirds of 32 elems ----
    for (int task = tid; task < TMROWS * 4; task += NT) {
        const int m = task >> 2, q = task & 3;
        if (q < 3) {
            const int gm = base + m;
            const int id = gm < n_atoms ? gm : n_atoms - 1;
            const int wbase = m * 52 + q * 16;
            if (q == 0) {
                float inv = 1.0f / g_cnt[id];
#pragma unroll
                for (int p = 0; p < 8; p++) {
                    float4 v = *(const float4*)&g_b2a[(size_t)id * 32 + 4 * p];
                    uint32_t hw, lw;
                    split_pair(v.x * inv, v.y * inv, hw, lw);
                    Xh[wbase + 2 * p] = hw; Xl[wbase + 2 * p] = lw;
                    split_pair(v.z * inv, v.w * inv, hw, lw);
                    Xh[wbase + 2 * p + 1] = hw; Xl[wbase + 2 * p + 1] = lw;
                }
            } else {
                const float* src = (q == 1) ? atoms + (size_t)id * 32 : state;
#pragma unroll
                for (int p = 0; p < 8; p++) {
                    float4 v = *(const float4*)(src + 4 * p);
                    uint32_t hw, lw;
                    split_pair(v.x, v.y, hw, lw);
                    Xh[wbase + 2 * p] = hw; Xl[wbase + 2 * p] = lw;
                    split_pair(v.z, v.w, hw, lw);
                    Xh[wbase + 2 * p + 1] = hw; Xl[wbase + 2 * p + 1] = lw;
                }
            }
        }
    }
    CP_WAIT0();
    __syncthreads();

    const uint32_t a_row = (uint32_t)(wm * 32 + (lane & 15));
    const uint32_t a_kb  = (uint32_t)((lane >> 4) << 4);
    const uint32_t b_row = (uint32_t)(((lane >> 4) << 3) + (lane & 7));
    const uint32_t b_kb  = (uint32_t)(((lane >> 3) & 1) << 4);

    // ---- layer 1: K=96 (strides 208B) ----
    {
        float acc[2][4][4];
        uint32_t ao = a_row * 208 + a_kb;
        uint32_t bo = (wn * 32 + b_row) * 208 + b_kb;
        mlp_layer2<6, 4>(sb + A_XB + ao, sb + A_XB + 26624 + ao, 208,
                         sb + A_WB + bo, 208, acc);
        __syncthreads();
        epi_to_h2<4>(acc, Bs, Hh, Hl, wm, wn, g, t);
    }
    __syncthreads();

    // ---- layer 2 ----
    {
        float acc[2][4][4];
        uint32_t ao = a_row * 144 + a_kb;
        uint32_t bo = (wn * 32 + b_row) * 144 + b_kb;
        mlp_layer2<4, 4>(sb + A_XB + ao, sb + A_XB + 18432 + ao, 144,
                         sb + A_WB + 13312 + bo, 144, acc);
        __syncthreads();
        epi_to_h2<4>(acc, Bs + 64, Hh, Hl, wm, wn, g, t);
    }
    __syncthreads();

    // ---- layer 3 ----
    {
        float acc[2][2][4];
        uint32_t ao = a_row * 144 + a_kb;
        uint32_t bo = (wn * 16 + b_row) * 144 + b_kb;
        mlp_layer2<4, 2>(sb + A_XB + ao, sb + A_XB + 18432 + ao, 144,
                         sb + A_WB + 22528 + bo, 144, acc);
        epi_to_f32_2(acc, Bs + 128, H3, wm, wn, g, t);
    }
    __syncthreads();

    for (int idx = tid; idx < TMROWS * 8; idx += NT) {
        int r = idx >> 3, f4 = idx & 7;
        if (base + r < n_atoms) {
            float4 v = *(float4*)&H3[r * 36 + (f4 << 2)];
            *(float4*)&out_atoms[(size_t)(base + r) * 32 + (f4 << 2)] = v;
        }
    }
    if (tid < 32) {
        float ssum = 0.f;
        for (int r = 0; r < TMROWS; r++)
            if (base + r < n_atoms) ssum += H3[r * 36 + tid];
        atomicAdd(&g_asum[tid], ssum);
    }
}

// ================= phi_u =================
__global__ void state_kernel(
    const float* __restrict__ state,
    const float* __restrict__ uw1, const float* __restrict__ ub1,
    const float* __restrict__ uw2, const float* __restrict__ ub2,
    const float* __restrict__ uw3, const float* __restrict__ ub3,
    float* __restrict__ out_state, int n_bonds, int n_atoms)
{
    __shared__ float x[96], h1[64], h2[64];
    int tid = threadIdx.x;  // 64 threads
    if (tid < 32) {
        x[tid]      = g_bsum[tid] / (float)n_bonds;
        x[32 + tid] = g_asum[tid] / (float)n_atoms;
        x[64 + tid] = state[tid];
    }
    __syncthreads();
    {
        float a = ub1[tid];
        for (int k = 0; k < 96; k++) a = fmaf(x[k], uw1[k * 64 + tid], a);
        h1[tid] = selu_f(a);
    }
    __syncthreads();
    {
        float a = ub2[tid];
        for (int k = 0; k < 64; k++) a = fmaf(h1[k], uw2[k * 64 + tid], a);
        h2[tid] = selu_f(a);
    }
    __syncthreads();
    if (tid < 32) {
        float a = ub3[tid];
        for (int k = 0; k < 64; k++) a = fmaf(h2[k], uw3[k * 32 + tid], a);
        out_state[tid] = selu_f(a);
    }
}

// ================= launch =================
extern "C" void kernel_launch(void* const* d_in, const int* in_sizes, int n_in,
                              void* d_out, int out_size)
{
    const float* bonds = (const float*)d_in[0];
    const int*   ba1   = (const int*)d_in[1];
    const int*   ba2   = (const int*)d_in[2];
    const float* atoms = (const float*)d_in[3];
    const float* state = (const float*)d_in[4];
    const float* ew1 = (const float*)d_in[5];
    const float* eb1 = (const float*)d_in[6];
    const float* ew2 = (const float*)d_in[7];
    const float* eb2 = (const float*)d_in[8];
    const float* ew3 = (const float*)d_in[9];
    const float* eb3 = (const float*)d_in[10];
    const float* vw1 = (const float*)d_in[11];
    const float* vb1 = (const float*)d_in[12];
    const float* vw2 = (const float*)d_in[13];
    const float* vb2 = (const float*)d_in[14];
    const float* vw3 = (const float*)d_in[15];
    const float* vb3 = (const float*)d_in[16];
    const float* uw1 = (const float*)d_in[17];
    const float* ub1 = (const float*)d_in[18];
    const float* uw2 = (const float*)d_in[19];
    const float* ub2 = (const float*)d_in[20];
    const float* uw3 = (const float*)d_in[21];
    const float* ub3 = (const float*)d_in[22];

    const int n_bonds = in_sizes[1];
    const int n_atoms = in_sizes[3] / 32;

    float* out       = (float*)d_out;
    float* out_bonds = out;
    float* out_atoms = out + (size_t)n_bonds * 32;
    float* out_state = out_atoms + (size_t)n_atoms * 32;

    cudaFuncSetAttribute(bond_kernel, cudaFuncAttributeMaxDynamicSharedMemorySize, B_SMEM);
    cudaFuncSetAttribute(atom_kernel, cudaFuncAttributeMaxDynamicSharedMemorySize, A_SMEM);

    zero_kernel<<<256, 256>>>(n_atoms);
    prep_kernel<<<(29184 + 255) / 256, 256>>>(ew1, ew2, ew3, vw1, vw2, vw3);

    int bond_blocks = n_bonds / TMROWS;
    bond_kernel<<<bond_blocks, NT, B_SMEM>>>(
        bonds, ba1, ba2, atoms, state, eb1, eb2, eb3, out_bonds, n_bonds);

    int atom_blocks = (n_atoms + TMROWS - 1) / TMROWS;
    atom_kernel<<<atom_blocks, NT, A_SMEM>>>(
        atoms, state, vb1, vb2, vb3, out_atoms, n_atoms);

    state_kernel<<<1, 64>>>(state, uw1, ub1, uw2, ub2, uw3, ub3,
                            out_state, n_bonds, n_atoms);
}

// round 10
// speedup vs baseline: 5.3895x; 1.0870x over previous
#include <cuda_runtime.h>
#include <cuda_fp16.h>
#include <math.h>
#include <stdint.h>

// ================= scratch (no allocations allowed) =================
#define MAX_ATOMS 100000
__device__ float g_b2a[MAX_ATOMS * 32];
__device__ float g_cnt[MAX_ATOMS];
__device__ float g_bsum[32];
__device__ float g_asum[32];

// pre-transposed fp16 weight images Wt[n][k], padded k-stride
__device__ __align__(16) __half g_we[15616];  // W1@0 W2@8704 W3@13312 (halves)
__device__ __align__(16) __half g_wv[13568];  // V1@0 V2@6656 V3@11264

__device__ __forceinline__ float selu_f(float x) {
    const float lam = 1.0507009873554805f;
    const float la  = 1.7580993408473766f;
    float e = __expf(x);
    return x > 0.f ? lam * x : fmaf(la, e, -la);
}

// fp32 pair -> fp16x2 hi word + fp16x2 residual word (packed cvt)
__device__ __forceinline__ void split_pair(float v0, float v1, uint32_t& hw, uint32_t& lw) {
    __half2 hp = __floats2half2_rn(v0, v1);
    float2 hf = __half22float2(hp);
    __half2 lp = __floats2half2_rn(v0 - hf.x, v1 - hf.y);
    hw = *(uint32_t*)&hp;
    lw = *(uint32_t*)&lp;
}

__device__ __forceinline__ uint32_t smem_u32(const void* p) {
    uint32_t a;
    asm("{ .reg .u64 t; cvta.to.shared.u64 t, %1; cvt.u32.u64 %0, t; }" : "=r"(a) : "l"(p));
    return a;
}

// ---- baseline-ISA ops (valid on plain sm_100) ----
__device__ __forceinline__ void ldmx4(uint32_t r[4], uint32_t addr) {
    asm volatile("ldmatrix.sync.aligned.m8n8.x4.shared.b16 {%0,%1,%2,%3}, [%4];"
        : "=r"(r[0]), "=r"(r[1]), "=r"(r[2]), "=r"(r[3]) : "r"(addr));
}
__device__ __forceinline__ void mma_f16(float c[4], const uint32_t a[4], uint32_t b0, uint32_t b1) {
    asm("mma.sync.aligned.m16n8k16.row.col.f32.f16.f16.f32 "
        "{%0,%1,%2,%3}, {%4,%5,%6,%7}, {%8,%9}, {%0,%1,%2,%3};"
        : "+f"(c[0]), "+f"(c[1]), "+f"(c[2]), "+f"(c[3])
        : "r"(a[0]), "r"(a[1]), "r"(a[2]), "r"(a[3]), "r"(b0), "r"(b1));
}
__device__ __forceinline__ void cp16(uint32_t dst, const void* src) {
    asm volatile("cp.async.ca.shared.global [%0], [%1], 16;" :: "r"(dst), "l"(src));
}
#define CP_COMMIT() asm volatile("cp.async.commit_group;" ::: "memory")
#define CP_WAIT0()  asm volatile("cp.async.wait_group 0;" ::: "memory")
// pair-scoped barrier: 2 warps (64 threads), ids 1..4
#define PAIR_BAR(wm) asm volatile("bar.sync %0, 64;" :: "r"((wm) + 1) : "memory")

// dense layer: acc[NTW][4] += A(16 rows x K) @ Wt^T  (fp16 2-pass)
template <int KS, int NTW>
__device__ __forceinline__ void mlp_layer(
    uint32_t xh_addr, uint32_t xl_addr,
    uint32_t b_addr, uint32_t sbwB,
    float acc[NTW][4])
{
#pragma unroll
    for (int j = 0; j < NTW; j++)
#pragma unroll
        for (int q = 0; q < 4; q++) acc[j][q] = 0.f;

#pragma unroll
    for (int k = 0; k < KS; k++) {
        uint32_t ah[4], al[4];
        ldmx4(ah, xh_addr);
        ldmx4(al, xl_addr);
        xh_addr += 32; xl_addr += 32;
#pragma unroll
        for (int p = 0; p < NTW / 2; p++) {
            uint32_t rw[4];
            ldmx4(rw, b_addr + p * 8 * sbwB * 2);
            mma_f16(acc[2 * p],     ah, rw[0], rw[1]);
            mma_f16(acc[2 * p + 1], ah, rw[2], rw[3]);
            mma_f16(acc[2 * p],     al, rw[0], rw[1]);
            mma_f16(acc[2 * p + 1], al, rw[2], rw[3]);
        }
        b_addr += 32;
    }
}

// epilogue: bias+selu -> split -> pair-LOCAL fp16 H images (rows 0..15, stride 36 words)
template <int NTW>
__device__ __forceinline__ void epi_to_h(
    float acc[NTW][4], const float* bias,
    uint32_t* Hh, uint32_t* Hl, int wn, int g, int t)
{
    const int r0 = g;  // local row within pair
#pragma unroll
    for (int j = 0; j < NTW; j++) {
        int col = wn * 32 + j * 8 + 2 * t;
        int cw  = wn * 16 + j * 4 + t;
        float b0 = bias[col], b1 = bias[col + 1];
        uint32_t hw, lw;
        split_pair(selu_f(acc[j][0] + b0), selu_f(acc[j][1] + b1), hw, lw);
        Hh[r0 * 36 + cw] = hw; Hl[r0 * 36 + cw] = lw;
        split_pair(selu_f(acc[j][2] + b0), selu_f(acc[j][3] + b1), hw, lw);
        Hh[(r0 + 8) * 36 + cw] = hw; Hl[(r0 + 8) * 36 + cw] = lw;
    }
}

// epilogue: bias+selu -> fp32 H3 [64][36] (global rows), N=32
__device__ __forceinline__ void epi_to_f32(
    float acc[2][4], const float* bias, float* H3, int wm, int wn, int g, int t)
{
    const int r0 = wm * 16 + g;
#pragma unroll
    for (int j = 0; j < 2; j++) {
        int col = wn * 16 + j * 8 + 2 * t;
        float b0 = bias[col], b1 = bias[col + 1];
        float2 v;
        v.x = selu_f(acc[j][0] + b0);
        v.y = selu_f(acc[j][1] + b1);
        *(float2*)&H3[r0 * 36 + col] = v;
        v.x = selu_f(acc[j][2] + b0);
        v.y = selu_f(acc[j][3] + b1);
        *(float2*)&H3[(r0 + 8) * 36 + col] = v;
    }
}

// ================= zero scratch =================
__global__ void zero_kernel(int n_atoms)
{
    int i = blockIdx.x * blockDim.x + threadIdx.x;
    int stride = gridDim.x * blockDim.x;
    int nb = n_atoms * 32;
    for (int idx = i; idx < nb; idx += stride) g_b2a[idx] = 0.f;
    for (int idx = i; idx < n_atoms; idx += stride) g_cnt[idx] = 0.f;
    if (i < 32) { g_bsum[i] = 0.f; g_asum[i] = 0.f; }
}

// ================= weight transpose prep =================
__global__ void prep_kernel(
    const float* __restrict__ ew1, const float* __restrict__ ew2, const float* __restrict__ ew3,
    const float* __restrict__ vw1, const float* __restrict__ vw2, const float* __restrict__ vw3)
{
    int i = blockIdx.x * blockDim.x + threadIdx.x;
    if (i >= 29184) return;
    const float* src; __half* img;
    int stride, N, Ksrc, local;
    if (i < 8704)        { local = i;         stride = 136; N = 64; Ksrc = 128; src = ew1; img = g_we; }
    else if (i < 13312)  { local = i - 8704;  stride = 72;  N = 64; Ksrc = 64;  src = ew2; img = g_we + 8704; }
    else if (i < 15616)  { local = i - 13312; stride = 72;  N = 32; Ksrc = 64;  src = ew3; img = g_we + 13312; }
    else if (i < 22272)  { local = i - 15616; stride = 104; N = 64; Ksrc = 96;  src = vw1; img = g_wv; }
    else if (i < 26880)  { local = i - 22272; stride = 72;  N = 64; Ksrc = 64;  src = vw2; img = g_wv + 6656; }
    else                 { local = i - 26880; stride = 72;  N = 32; Ksrc = 64;  src = vw3; img = g_wv + 11264; }
    int n = local / stride, k = local % stride;
    float w = (k < Ksrc) ? src[k * N + n] : 0.f;
    img[local] = __float2half(w);
}

// ================= smem maps (bytes) =================
// bond: Xh 17408 + Xl 17408 (pair w's H overlays its own 4352B X range)
// H3 @ B_XB+34816 (9216); weights @ B_XB+44032 (31232)
#define B_BIAS   0
#define B_A1S    640
#define B_XB     1024
#define B_WB     45056
#define B_SMEM   76288
// atom: Xh 13312 + Xl 13312; H3 @ A_XB+26624; weights @ 36608
#define A_BIAS   0
#define A_XB     768
#define A_WB     36608
#define A_SMEM   63744

#define NT 256
#define TMROWS 64

// ================= phi_e over bonds =================
__global__ void __launch_bounds__(NT, 3) bond_kernel(
    const float* __restrict__ bonds, const int* __restrict__ ba1,
    const int* __restrict__ ba2, const float* __restrict__ atoms,
    const float* __restrict__ state,
    const float* __restrict__ eb1, const float* __restrict__ eb2,
    const float* __restrict__ eb3,
    float* __restrict__ out_bonds, int n_bonds)
{
    extern __shared__ char smem[];
    const uint32_t sb = smem_u32(smem);
    const int tid  = threadIdx.x;
    const int wid  = tid >> 5;
    const int lane = tid & 31;
    const int g = lane >> 2, t = lane & 3;
    const int wm = wid >> 1, wn = wid & 1;   // 4 pairs x 2 n-warps
    const int base = blockIdx.x * TMROWS;

    float* Bs  = (float*)(smem + B_BIAS);
    int*   A1s = (int*)(smem + B_A1S);
    uint32_t* Xh = (uint32_t*)(smem + B_XB);
    uint32_t* Xl = (uint32_t*)(smem + B_XB + 17408);
    // pair-local H (inside own X range)
    uint32_t* Hh = Xh + wm * 1088;
    uint32_t* Hl = Xl + wm * 1088;
    float*    H3 = (float*)(smem + B_XB + 34816);

    // weights -> smem (cp.async)
    for (int i = tid; i < 31232 / 16; i += NT)
        cp16(sb + B_WB + i * 16, (const char*)g_we + i * 16);
    CP_COMMIT();
    if (tid < 64) { Bs[tid] = eb1[tid]; Bs[64 + tid] = eb2[tid]; }
    else if (tid < 96) Bs[128 + tid - 64] = eb3[tid - 64];

    // ---- stage X: 64 rows x 4 quarters ----
    {
        const int m = tid >> 2, q = tid & 3;
        const int gid = base + m;
        const float* src;
        if (q == 0) {
            int a1 = ba1[gid];
            A1s[m] = a1;
            atomicAdd(&g_cnt[a1], 1.0f);
            src = atoms + (size_t)a1 * 32;
        } else if (q == 1) {
            src = atoms + (size_t)ba2[gid] * 32;
        } else if (q == 2) {
            src = bonds + (size_t)gid * 32;
        } else {
            src = state;
        }
        const int wbase = m * 68 + q * 16;
#pragma unroll
        for (int p = 0; p < 8; p++) {
            float4 v = *(const float4*)(src + 4 * p);
            uint32_t hw, lw;
            split_pair(v.x, v.y, hw, lw);
            Xh[wbase + 2 * p] = hw; Xl[wbase + 2 * p] = lw;
            split_pair(v.z, v.w, hw, lw);
            Xh[wbase + 2 * p + 1] = hw; Xl[wbase + 2 * p + 1] = lw;
        }
    }
    CP_WAIT0();
    __syncthreads();

    // lane-resolved fragment offsets
    const uint32_t a_loc = (uint32_t)(lane & 15);          // local row in pair
    const uint32_t a_kb  = (uint32_t)((lane >> 4) << 4);
    const uint32_t b_row = (uint32_t)(((lane >> 4) << 3) + (lane & 7));
    const uint32_t b_kb  = (uint32_t)(((lane >> 3) & 1) << 4);
    const uint32_t hb_h  = sb + B_XB + (uint32_t)wm * 4352;          // pair H hi base
    const uint32_t hb_l  = sb + B_XB + 17408 + (uint32_t)wm * 4352;  // pair H lo base

    // ---- layer 1: K=128 (X stride 272B), W1 stride 272B ----
    {
        float acc[4][4];
        uint32_t ao = ((uint32_t)(wm * 16) + a_loc) * 272 + a_kb;
        uint32_t bo = (wn * 32 + b_row) * 272 + b_kb;
        mlp_layer<8, 4>(sb + B_XB + ao, sb + B_XB + 17408 + ao,
                        sb + B_WB + bo, 272, acc);
        PAIR_BAR(wm);  // pair done reading its X rows
        epi_to_h<4>(acc, Bs, Hh, Hl, wn, g, t);
    }
    PAIR_BAR(wm);

    // ---- layer 2: K=64 (H stride 144B), W2 stride 144B ----
    {
        float acc[4][4];
        uint32_t ao = a_loc * 144 + a_kb;
        uint32_t bo = (wn * 32 + b_row) * 144 + b_kb;
        mlp_layer<4, 4>(hb_h + ao, hb_l + ao,
                        sb + B_WB + 17408 + bo, 144, acc);
        PAIR_BAR(wm);  // pair done reading H1
        epi_to_h<4>(acc, Bs + 64, Hh, Hl, wn, g, t);
    }
    PAIR_BAR(wm);

    // ---- layer 3: K=64, N=32 ----
    {
        float acc[2][4];
        uint32_t ao = a_loc * 144 + a_kb;
        uint32_t bo = (wn * 16 + b_row) * 144 + b_kb;
        mlp_layer<4, 2>(hb_h + ao, hb_l + ao,
                        sb + B_WB + 26624 + bo, 144, acc);
        epi_to_f32(acc, Bs + 128, H3, wm, wn, g, t);
    }
    __syncthreads();

    // ---- outputs ----
    for (int idx = tid; idx < TMROWS * 8; idx += NT) {
        int r = idx >> 3, f4 = idx & 7;
        float4 v = *(float4*)&H3[r * 36 + (f4 << 2)];
        *(float4*)&out_bonds[(size_t)(base + r) * 32 + (f4 << 2)] = v;
    }
    for (int r = wid; r < TMROWS; r += 8)
        atomicAdd(&g_b2a[(size_t)A1s[r] * 32 + lane], H3[r * 36 + lane]);
    if (tid < 32) {
        float ssum = 0.f;
        for (int r = 0; r < TMROWS; r++) ssum += H3[r * 36 + tid];
        atomicAdd(&g_bsum[tid], ssum);
    }
}

// ================= phi_v over atoms =================
__global__ void __launch_bounds__(NT, 3) atom_kernel(
    const float* __restrict__ atoms, const float* __restrict__ state,
    const float* __restrict__ vb1, const float* __restrict__ vb2,
    const float* __restrict__ vb3,
    float* __restrict__ out_atoms, int n_atoms)
{
    extern __shared__ char smem[];
    const uint32_t sb = smem_u32(smem);
    const int tid  = threadIdx.x;
    const int wid  = tid >> 5;
    const int lane = tid & 31;
    const int g = lane >> 2, t = lane & 3;
    const int wm = wid >> 1, wn = wid & 1;
    const int base = blockIdx.x * TMROWS;

    float* Bs = (float*)(smem + A_BIAS);
    uint32_t* Xh = (uint32_t*)(smem + A_XB);
    uint32_t* Xl = (uint32_t*)(smem + A_XB + 13312);
    uint32_t* Hh = Xh + wm * 832;   // pair X range = 16*52 = 832 words
    uint32_t* Hl = Xl + wm * 832;
    float*    H3 = (float*)(smem + A_XB + 26624);

    for (int i = tid; i < 27136 / 16; i += NT)
        cp16(sb + A_WB + i * 16, (const char*)g_wv + i * 16);
    CP_COMMIT();
    if (tid < 64) { Bs[tid] = vb1[tid]; Bs[64 + tid] = vb2[tid]; }
    else if (tid < 96) Bs[128 + tid - 64] = vb3[tid - 64];

    // ---- stage X: 64 rows x 3 thirds (quarter 3 idle) ----
    {
        const int m = tid >> 2, q = tid & 3;
        if (q < 3) {
            const int gm = base + m;
            const int id = gm < n_atoms ? gm : n_atoms - 1;
            const int wbase = m * 52 + q * 16;
            if (q == 0) {
                float inv = 1.0f / g_cnt[id];
#pragma unroll
                for (int p = 0; p < 8; p++) {
                    float4 v = *(const float4*)&g_b2a[(size_t)id * 32 + 4 * p];
                    uint32_t hw, lw;
                    split_pair(v.x * inv, v.y * inv, hw, lw);
                    Xh[wbase + 2 * p] = hw; Xl[wbase + 2 * p] = lw;
                    split_pair(v.z * inv, v.w * inv, hw, lw);
                    Xh[wbase + 2 * p + 1] = hw; Xl[wbase + 2 * p + 1] = lw;
                }
            } else {
                const float* src = (q == 1) ? atoms + (size_t)id * 32 : state;
#pragma unroll
                for (int p = 0; p < 8; p++) {
                    float4 v = *(const float4*)(src + 4 * p);
                    uint32_t hw, lw;
                    split_pair(v.x, v.y, hw, lw);
                    Xh[wbase + 2 * p] = hw; Xl[wbase + 2 * p] = lw;
                    split_pair(v.z, v.w, hw, lw);
                    Xh[wbase + 2 * p + 1] = hw; Xl[wbase + 2 * p + 1] = lw;
                }
            }
        }
    }
    CP_WAIT0();
    __syncthreads();

    const uint32_t a_loc = (uint32_t)(lane & 15);
    const uint32_t a_kb  = (uint32_t)((lane >> 4) << 4);
    const uint32_t b_row = (uint32_t)(((lane >> 4) << 3) + (lane & 7));
    const uint32_t b_kb  = (uint32_t)(((lane >> 3) & 1) << 4);
    const uint32_t hb_h  = sb + A_XB + (uint32_t)wm * 3328;
    const uint32_t hb_l  = sb + A_XB + 13312 + (uint32_t)wm * 3328;

    // ---- layer 1: K=96 (X stride 208B) ----
    {
        float acc[4][4];
        uint32_t ao = ((uint32_t)(wm * 16) + a_loc) * 208 + a_kb;
        uint32_t bo = (wn * 32 + b_row) * 208 + b_kb;
        mlp_layer<6, 4>(sb + A_XB + ao, sb + A_XB + 13312 + ao,
                        sb + A_WB + bo, 208, acc);
        PAIR_BAR(wm);
        epi_to_h<4>(acc, Bs, Hh, Hl, wn, g, t);
    }
    PAIR_BAR(wm);

    // ---- layer 2 ----
    {
        float acc[4][4];
        uint32_t ao = a_loc * 144 + a_kb;
        uint32_t bo = (wn * 32 + b_row) * 144 + b_kb;
        mlp_layer<4, 4>(hb_h + ao, hb_l + ao,
                        sb + A_WB + 13312 + bo, 144, acc);
        PAIR_BAR(wm);
        epi_to_h<4>(acc, Bs + 64, Hh, Hl, wn, g, t);
    }
    PAIR_BAR(wm);

    // ---- layer 3 ----
    {
        float acc[2][4];
        uint32_t ao = a_loc * 144 + a_kb;
        uint32_t bo = (wn * 16 + b_row) * 144 + b_kb;
        mlp_layer<4, 2>(hb_h + ao, hb_l + ao,
                        sb + A_WB + 22528 + bo, 144, acc);
        epi_to_f32(acc, Bs + 128, H3, wm, wn, g, t);
    }
    __syncthreads();

    for (int idx = tid; idx < TMROWS * 8; idx += NT) {
        int r = idx >> 3, f4 = idx & 7;
        if (base + r < n_atoms) {
            float4 v = *(float4*)&H3[r * 36 + (f4 << 2)];
            *(float4*)&out_atoms[(size_t)(base + r) * 32 + (f4 << 2)] = v;
        }
    }
    if (tid < 32) {
        float ssum = 0.f;
        for (int r = 0; r < TMROWS; r++)
            if (base + r < n_atoms) ssum += H3[r * 36 + tid];
        atomicAdd(&g_asum[tid], ssum);
    }
}

// ================= phi_u =================
__global__ void state_kernel(
    const float* __restrict__ state,
    const float* __restrict__ uw1, const float* __restrict__ ub1,
    const float* __restrict__ uw2, const float* __restrict__ ub2,
    const float* __restrict__ uw3, const float* __restrict__ ub3,
    float* __restrict__ out_state, int n_bonds, int n_atoms)
{
    __shared__ float x[96], h1[64], h2[64];
    int tid = threadIdx.x;  // 64 threads
    if (tid < 32) {
        x[tid]      = g_bsum[tid] / (float)n_bonds;
        x[32 + tid] = g_asum[tid] / (float)n_atoms;
        x[64 + tid] = state[tid];
    }
    __syncthreads();
    {
        float a = ub1[tid];
        for (int k = 0; k < 96; k++) a = fmaf(x[k], uw1[k * 64 + tid], a);
        h1[tid] = selu_f(a);
    }
    __syncthreads();
    {
        float a = ub2[tid];
        for (int k = 0; k < 64; k++) a = fmaf(h1[k], uw2[k * 64 + tid], a);
        h2[tid] = selu_f(a);
    }
    __syncthreads();
    if (tid < 32) {
        float a = ub3[tid];
        for (int k = 0; k < 64; k++) a = fmaf(h2[k], uw3[k * 32 + tid], a);
        out_state[tid] = selu_f(a);
    }
}

// ================= launch =================
extern "C" void kernel_launch(void* const* d_in, const int* in_sizes, int n_in,
                              void* d_out, int out_size)
{
    const float* bonds = (const float*)d_in[0];
    const int*   ba1   = (const int*)d_in[1];
    const int*   ba2   = (const int*)d_in[2];
    const float* atoms = (const float*)d_in[3];
    const float* state = (const float*)d_in[4];
    const float* ew1 = (const float*)d_in[5];
    const float* eb1 = (const float*)d_in[6];
    const float* ew2 = (const float*)d_in[7];
    const float* eb2 = (const float*)d_in[8];
    const float* ew3 = (const float*)d_in[9];
    const float* eb3 = (const float*)d_in[10];
    const float* vw1 = (const float*)d_in[11];
    const float* vb1 = (const float*)d_in[12];
    const float* vw2 = (const float*)d_in[13];
    const float* vb2 = (const float*)d_in[14];
    const float* vw3 = (const float*)d_in[15];
    const float* vb3 = (const float*)d_in[16];
    const float* uw1 = (const float*)d_in[17];
    const float* ub1 = (const float*)d_in[18];
    const float* uw2 = (const float*)d_in[19];
    const float* ub2 = (const float*)d_in[20];
    const float* uw3 = (const float*)d_in[21];
    const float* ub3 = (const float*)d_in[22];

    const int n_bonds = in_sizes[1];
    const int n_atoms = in_sizes[3] / 32;

    float* out       = (float*)d_out;
    float* out_bonds = out;
    float* out_atoms = out + (size_t)n_bonds * 32;
    float* out_state = out_atoms + (size_t)n_atoms * 32;

    cudaFuncSetAttribute(bond_kernel, cudaFuncAttributeMaxDynamicSharedMemorySize, B_SMEM);
    cudaFuncSetAttribute(atom_kernel, cudaFuncAttributeMaxDynamicSharedMemorySize, A_SMEM);

    zero_kernel<<<256, 256>>>(n_atoms);
    prep_kernel<<<(29184 + 255) / 256, 256>>>(ew1, ew2, ew3, vw1, vw2, vw3);

    int bond_blocks = n_bonds / TMROWS;
    bond_kernel<<<bond_blocks, NT, B_SMEM>>>(
        bonds, ba1, ba2, atoms, state, eb1, eb2, eb3, out_bonds, n_bonds);

    int atom_blocks = (n_atoms + TMROWS - 1) / TMROWS;
    atom_kernel<<<atom_blocks, NT, A_SMEM>>>(
        atoms, state, vb1, vb2, vb3, out_atoms, n_atoms);

    state_kernel<<<1, 64>>>(state, uw1, ub1, uw2, ub2, uw3, ub3,
                            out_state, n_bonds, n_atoms);
}